// round 11
// baseline (speedup 1.0000x reference)
#include <cuda_runtime.h>
#include <cuda_fp16.h>
#include <stdint.h>

#define BB 4
#define SS 2048
#define DD 1024
#define HH 16
#define HDIM 64
#define MM (BB*SS)   // 8192

// Scratch (allocation-free rule: __device__ globals). All fp16.
__device__ __half g_Xt[(size_t)MM*DD];
__device__ __half g_Wt[(size_t)4*DD*DD];    // wq,wk,wv,wo
__device__ __half g_Q [(size_t)MM*DD];      // [B,H,S,HD]
__device__ __half g_K [(size_t)MM*DD];
__device__ __half g_V [(size_t)MM*DD];      // TRANSPOSED: [B,H,HD,S]
__device__ __half g_AO[(size_t)MM*DD];      // [B,S,D]

__device__ __forceinline__ float ex2(float x) {
    float r;
    asm("ex2.approx.f32 %0, %1;" : "=f"(r) : "f"(x));
    return r;
}
__device__ __forceinline__ uint32_t h2(float a, float b) {
    __half2 h = __floats2half2_rn(a, b);
    return *(uint32_t*)&h;
}
__device__ __forceinline__ void mmaf16(float* c, const uint32_t* a, const uint32_t* b) {
    asm volatile(
        "mma.sync.aligned.m16n8k16.row.col.f32.f16.f16.f32 "
        "{%0,%1,%2,%3},{%4,%5,%6,%7},{%8,%9},{%0,%1,%2,%3};"
        : "+f"(c[0]), "+f"(c[1]), "+f"(c[2]), "+f"(c[3])
        : "r"(a[0]), "r"(a[1]), "r"(a[2]), "r"(a[3]), "r"(b[0]), "r"(b[1]));
}
#define LDSM4(r0, r1, r2, r3, addr) \
    asm volatile("ldmatrix.sync.aligned.m8n8.x4.shared.b16 {%0,%1,%2,%3}, [%4];" \
                 : "=r"(r0), "=r"(r1), "=r"(r2), "=r"(r3) : "r"(addr))
__device__ __forceinline__ void cpa16(uint32_t dst, const void* src) {
    asm volatile("cp.async.cg.shared.global [%0], [%1], 16;" :: "r"(dst), "l"(src));
}
__device__ __forceinline__ void cpcommit() {
    asm volatile("cp.async.commit_group;");
}
template<int N> __device__ __forceinline__ void cpwait() {
    asm volatile("cp.async.wait_group %0;" :: "n"(N));
}

// ---------------------------------------------------------------------------
// Fused prepass: fp32 -> fp16 (RN) for x + all 4 weights, one launch.
// ---------------------------------------------------------------------------
#define N4X (MM*DD/4)       // 2097152
#define N4W (DD*DD/4)       // 262144 = 2^18
__global__ void cvt_all(const float4* __restrict__ x,
                        const float4* __restrict__ wq, const float4* __restrict__ wk,
                        const float4* __restrict__ wv, const float4* __restrict__ wo) {
    int i = blockIdx.x * 256 + threadIdx.x;
    const float4* src;
    __half* dst;
    int j;
    if (i < N4X) {
        src = x; dst = g_Xt; j = i;
    } else {
        int k = i - N4X;
        int w = k >> 18;
        j = k & (N4W - 1);
        src = (w == 0) ? wq : (w == 1) ? wk : (w == 2) ? wv : wo;
        dst = g_Wt + (size_t)w * DD * DD;
    }
    float4 v = src[j];
    *(uint2*)&dst[(size_t)j * 4] = make_uint2(h2(v.x, v.y), h2(v.z, v.w));
}

// ---------------------------------------------------------------------------
// Shared GEMM mainloop: acc = A[M,K] @ B[N,K]^T for one 128x128 tile.
// K-slab 64, 2-stage cp.async. Smem halfs: stage s at s*18432; A stride 72,
// B at +9216 halfs. Fragments via ldmatrix.x4.
// ---------------------------------------------------------------------------
__device__ __forceinline__ void g_load(uint32_t smb, int s,
                                       const __half* Ag, const __half* Bg,
                                       int m0, int n0, int k0, int tid) {
    uint32_t sa = smb + (uint32_t)s * 36864u;
    uint32_t sb = sa + 18432u;
    #pragma unroll
    for (int i = 0; i < 4; i++) {
        int c = tid + i * 256;
        int r = c >> 3, cb = (c & 7) * 16;
        cpa16(sa + (uint32_t)(r * 144 + cb), Ag + (size_t)(m0 + r) * DD + k0 + (c & 7) * 8);
    }
    #pragma unroll
    for (int i = 0; i < 4; i++) {
        int c = tid + i * 256;
        int r = c >> 3, cb = (c & 7) * 16;
        cpa16(sb + (uint32_t)(r * 144 + cb), Bg + (size_t)(n0 + r) * DD + k0 + (c & 7) * 8);
    }
    cpcommit();
}

__device__ __forceinline__ void run_gemm(float acc[2][8][4],
                                         const __half* Ag, const __half* Bg,
                                         int m0, int n0, __half* smh, int tid)
{
    const int warp = tid >> 5, lane = tid & 31;
    const int wm = warp & 3, wn = warp >> 2;
    const uint32_t smb = (uint32_t)__cvta_generic_to_shared(smh);
    // ldmatrix lane offsets (bytes)
    const uint32_t a_off = (uint32_t)((wm * 32 + (lane & 15)) * 144 + (lane & 16));
    const uint32_t b_off = (uint32_t)(18432 +
        (wn * 64 + (lane & 7) + ((lane & 16) >> 1)) * 144 + (lane & 8) * 2);

    g_load(smb, 0, Ag, Bg, m0, n0, 0, tid);

    for (int t = 0; t < 16; t++) {
        const int s = t & 1;
        if (t < 15) {
            g_load(smb, s ^ 1, Ag, Bg, m0, n0, (t + 1) * 64, tid);
            cpwait<1>();
        } else {
            cpwait<0>();
        }
        __syncthreads();

        const uint32_t sa = smb + (uint32_t)s * 36864u + a_off;
        const uint32_t sb = smb + (uint32_t)s * 36864u + b_off;
        #pragma unroll
        for (int ks = 0; ks < 4; ks++) {
            uint32_t a[2][4], b[8][2];
            LDSM4(a[0][0], a[0][1], a[0][2], a[0][3], sa + ks * 32);
            LDSM4(a[1][0], a[1][1], a[1][2], a[1][3], sa + 2304 + ks * 32);
            #pragma unroll
            for (int n2 = 0; n2 < 4; n2++)
                LDSM4(b[2*n2][0], b[2*n2][1], b[2*n2+1][0], b[2*n2+1][1],
                      sb + n2 * 2304 + ks * 32);
            #pragma unroll
            for (int mi = 0; mi < 2; mi++)
                #pragma unroll
                for (int ni = 0; ni < 8; ni++)
                    mmaf16(acc[mi][ni], a[mi], b[ni]);
        }
        __syncthreads();
    }
}

// ---------------------------------------------------------------------------
// Fused QKV projection: z = 0/1/2 -> Q/K (RoPE) / V (transposed write).
// ---------------------------------------------------------------------------
__global__ __launch_bounds__(256, 2)
void qkv_f16(const float* __restrict__ fc, const float* __restrict__ fs)
{
    extern __shared__ __half smh[];
    const int tid = threadIdx.x;
    const int m0 = blockIdx.y * 128, n0 = blockIdx.x * 128;
    const int z = blockIdx.z;
    const int warp = tid >> 5, lane = tid & 31;
    const int wm = warp & 3, wn = warp >> 2;
    const int g = lane >> 2, tig = lane & 3;

    float acc[2][8][4];
    #pragma unroll
    for (int mi = 0; mi < 2; mi++)
        #pragma unroll
        for (int ni = 0; ni < 8; ni++)
            #pragma unroll
            for (int j = 0; j < 4; j++) acc[mi][ni][j] = 0.f;

    run_gemm(acc, g_Xt, g_Wt + (size_t)z * DD * DD, m0, n0, smh, tid);

    #pragma unroll
    for (int mi = 0; mi < 2; mi++) {
        #pragma unroll
        for (int ni = 0; ni < 8; ni++) {
            const int m = m0 + wm * 32 + mi * 16 + g;
            const int n = n0 + wn * 64 + ni * 8 + 2 * tig;
            float c0 = acc[mi][ni][0], c1 = acc[mi][ni][1];
            float c2 = acc[mi][ni][2], c3 = acc[mi][ni][3];
            const int b = m >> 11, sl = m & (SS - 1);
            const int h = n >> 6, d = n & 63;
            const int bh = b * HH + h;
            if (z == 2) {
                size_t ov = ((size_t)bh * HDIM + d) * SS + sl;
                g_V[ov]          = __float2half_rn(c0);
                g_V[ov + SS]     = __float2half_rn(c1);
                g_V[ov + 8]      = __float2half_rn(c2);
                g_V[ov + SS + 8] = __float2half_rn(c3);
            } else {
                const int f = d >> 1;
                float cA = fc[sl * 32 + f],       sA = fs[sl * 32 + f];
                float cB = fc[(sl + 8) * 32 + f], sB = fs[(sl + 8) * 32 + f];
                float v0 = c0 * cA - c1 * sA, v1 = c0 * sA + c1 * cA;
                float v2 = c2 * cB - c3 * sB, v3 = c2 * sB + c3 * cB;
                __half* dstq = (z == 0) ? g_Q : g_K;
                size_t o = ((size_t)bh * SS + sl) * HDIM + d;
                *(uint32_t*)&dstq[o]            = h2(v0, v1);
                *(uint32_t*)&dstq[o + 8 * HDIM] = h2(v2, v3);
            }
        }
    }
}

// ---------------------------------------------------------------------------
// Output projection: g_AO @ wo -> fp32 out.
// ---------------------------------------------------------------------------
__global__ __launch_bounds__(256, 2)
void gemm_o(float* __restrict__ out)
{
    extern __shared__ __half smh[];
    const int tid = threadIdx.x;
    const int m0 = blockIdx.y * 128, n0 = blockIdx.x * 128;
    const int warp = tid >> 5, lane = tid & 31;
    const int wm = warp & 3, wn = warp >> 2;
    const int g = lane >> 2, tig = lane & 3;

    float acc[2][8][4];
    #pragma unroll
    for (int mi = 0; mi < 2; mi++)
        #pragma unroll
        for (int ni = 0; ni < 8; ni++)
            #pragma unroll
            for (int j = 0; j < 4; j++) acc[mi][ni][j] = 0.f;

    run_gemm(acc, g_AO, g_Wt + (size_t)3 * DD * DD, m0, n0, smh, tid);

    #pragma unroll
    for (int mi = 0; mi < 2; mi++) {
        #pragma unroll
        for (int ni = 0; ni < 8; ni++) {
            const int m = m0 + wm * 32 + mi * 16 + g;
            const int n = n0 + wn * 64 + ni * 8 + 2 * tig;
            *(float2*)&out[(size_t)m * DD + n] =
                make_float2(acc[mi][ni][0], acc[mi][ni][1]);
            *(float2*)&out[(size_t)(m + 8) * DD + n] =
                make_float2(acc[mi][ni][2], acc[mi][ni][3]);
        }
    }
}

// ---------------------------------------------------------------------------
// Flash attention fp16. 256 thr = 2 q-groups x 4 warps; 128 q rows/CTA;
// 64-key tiles double-buffered; fragments via ldmatrix.x4; P in registers.
// Smem halfs: Ks[s] at s*4608 (64x72), Vt[s] at 9216 + s*4608. 36864 B.
// ---------------------------------------------------------------------------
__device__ __forceinline__ void attn_load(uint32_t smb, int stage,
                                          const __half* Kg, const __half* Vtg,
                                          int kt, int tid) {
    uint32_t ks = smb + (uint32_t)stage * 9216u;
    uint32_t vs = smb + 18432u + (uint32_t)stage * 9216u;
    #pragma unroll
    for (int i = 0; i < 2; i++) {
        int c = tid + i * 256;
        int r = c >> 3, cb = (c & 7) * 16;
        cpa16(ks + (uint32_t)(r * 144 + cb), Kg + (size_t)(kt * 64 + r) * HDIM + (c & 7) * 8);
        cpa16(vs + (uint32_t)(r * 144 + cb), Vtg + (size_t)r * SS + kt * 64 + (c & 7) * 8);
    }
}

#define SCL 0.18033688f   // 0.125 * log2(e)

__global__ __launch_bounds__(256, 2)
void attn_f16()
{
    extern __shared__ __half smh[];
    const int tid = threadIdx.x, warp = tid >> 5, lane = tid & 31;
    const int g = lane >> 2, tig = lane & 3;
    const int gid = warp >> 2, w4 = warp & 3;
    const int qb = gridDim.x - 1 - blockIdx.x;   // heaviest tiles first
    const int bh = blockIdx.y;
    const size_t base = (size_t)bh * SS * HDIM;
    const int mylim = 2 * qb + gid;
    const int lim = 2 * qb + 1;
    const int row0 = qb * 128 + gid * 64 + w4 * 16 + g;
    const int row1 = row0 + 8;
    const uint32_t smb = (uint32_t)__cvta_generic_to_shared(smh);
    // ldmatrix lane offset for K/Vt fragment loads (bytes)
    const uint32_t f_off = (uint32_t)(
        ((lane & 7) + ((lane & 16) >> 1)) * 144 + (lane & 8) * 2);

    // Q fragments direct from gmem (fp16). aq[kk] covers dims 16kk..16kk+15.
    uint32_t aq[4][4];
    {
        const __half* Q0 = g_Q + base + (size_t)row0 * HDIM;
        #pragma unroll
        for (int kk = 0; kk < 4; kk++) {
            int c = kk * 16 + 2 * tig;
            aq[kk][0] = *(const uint32_t*)&Q0[c];
            aq[kk][1] = *(const uint32_t*)&Q0[8 * HDIM + c];
            aq[kk][2] = *(const uint32_t*)&Q0[c + 8];
            aq[kk][3] = *(const uint32_t*)&Q0[8 * HDIM + c + 8];
        }
    }

    float oacc[8][4];
    #pragma unroll
    for (int ni = 0; ni < 8; ni++)
        #pragma unroll
        for (int j = 0; j < 4; j++) oacc[ni][j] = 0.f;
    float m0 = -1e30f, m1 = -1e30f, l0 = 0.f, l1 = 0.f;

    const __half* Kg  = g_K + base;
    const __half* Vtg = g_V + base;

    attn_load(smb, 0, Kg, Vtg, 0, tid);
    cpcommit();

    for (int kt = 0; kt <= lim; kt++) {
        const int s = kt & 1;
        if (kt < lim) {
            attn_load(smb, s ^ 1, Kg, Vtg, kt + 1, tid);
            cpcommit();
            cpwait<1>();
        } else {
            cpwait<0>();
        }
        __syncthreads();

        if (kt <= mylim) {
            const uint32_t kbase = smb + (uint32_t)s * 9216u + f_off;
            const uint32_t vbase = smb + 18432u + (uint32_t)s * 9216u + f_off;

            // S = Q @ K^T  (keys = n, dims = k)
            float sc[8][4];
            #pragma unroll
            for (int ni = 0; ni < 8; ni++)
                #pragma unroll
                for (int j = 0; j < 4; j++) sc[ni][j] = 0.f;
            #pragma unroll
            for (int kk = 0; kk < 4; kk++) {
                uint32_t b[8][2];
                #pragma unroll
                for (int n2 = 0; n2 < 4; n2++)
                    LDSM4(b[2*n2][0], b[2*n2][1], b[2*n2+1][0], b[2*n2+1][1],
                          kbase + n2 * 2304 + kk * 32);
                #pragma unroll
                for (int ni = 0; ni < 8; ni++) mmaf16(sc[ni], aq[kk], b[ni]);
            }

            // scale (log2 domain) + causal mask on diagonal tile + row max
            const bool diag = (kt == mylim);
            float nm0 = m0, nm1 = m1;
            #pragma unroll
            for (int ni = 0; ni < 8; ni++) {
                int col = kt * 64 + ni * 8 + 2 * tig;
                #pragma unroll
                for (int j = 0; j < 4; j++) sc[ni][j] *= SCL;
                if (diag) {
                    if (col     > row0) sc[ni][0] = -1e30f;
                    if (col + 1 > row0) sc[ni][1] = -1e30f;
                    if (col     > row1) sc[ni][2] = -1e30f;
                    if (col + 1 > row1) sc[ni][3] = -1e30f;
                }
                nm0 = fmaxf(nm0, fmaxf(sc[ni][0], sc[ni][1]));
                nm1 = fmaxf(nm1, fmaxf(sc[ni][2], sc[ni][3]));
            }
            nm0 = fmaxf(nm0, __shfl_xor_sync(0xffffffffu, nm0, 1));
            nm0 = fmaxf(nm0, __shfl_xor_sync(0xffffffffu, nm0, 2));
            nm1 = fmaxf(nm1, __shfl_xor_sync(0xffffffffu, nm1, 1));
            nm1 = fmaxf(nm1, __shfl_xor_sync(0xffffffffu, nm1, 2));
            const float corr0 = ex2(m0 - nm0), corr1 = ex2(m1 - nm1);
            m0 = nm0; m1 = nm1;

            // exp; P stays in registers (fp16 C->A fragment identity)
            float ps[8][4];
            float ls0 = 0.f, ls1 = 0.f;
            #pragma unroll
            for (int ni = 0; ni < 8; ni++) {
                ps[ni][0] = ex2(sc[ni][0] - m0);
                ps[ni][1] = ex2(sc[ni][1] - m0);
                ps[ni][2] = ex2(sc[ni][2] - m1);
                ps[ni][3] = ex2(sc[ni][3] - m1);
                ls0 += ps[ni][0] + ps[ni][1];
                ls1 += ps[ni][2] + ps[ni][3];
            }
            l0 = l0 * corr0 + ls0;
            l1 = l1 * corr1 + ls1;
            #pragma unroll
            for (int ni = 0; ni < 8; ni++) {
                oacc[ni][0] *= corr0; oacc[ni][1] *= corr0;
                oacc[ni][2] *= corr1; oacc[ni][3] *= corr1;
            }

            // O += P @ V  (dims = n via Vt rows, keys = k)
            #pragma unroll
            for (int kk = 0; kk < 4; kk++) {
                uint32_t pa[4];
                pa[0] = h2(ps[2*kk][0],   ps[2*kk][1]);
                pa[1] = h2(ps[2*kk][2],   ps[2*kk][3]);
                pa[2] = h2(ps[2*kk+1][0], ps[2*kk+1][1]);
                pa[3] = h2(ps[2*kk+1][2], ps[2*kk+1][3]);
                uint32_t b[8][2];
                #pragma unroll
                for (int n2 = 0; n2 < 4; n2++)
                    LDSM4(b[2*n2][0], b[2*n2][1], b[2*n2+1][0], b[2*n2+1][1],
                          vbase + n2 * 2304 + kk * 32);
                #pragma unroll
                for (int ni = 0; ni < 8; ni++) mmaf16(oacc[ni], pa, b[ni]);
            }
        }
        __syncthreads();
    }

    // Finalize
    l0 += __shfl_xor_sync(0xffffffffu, l0, 1);
    l0 += __shfl_xor_sync(0xffffffffu, l0, 2);
    l1 += __shfl_xor_sync(0xffffffffu, l1, 1);
    l1 += __shfl_xor_sync(0xffffffffu, l1, 2);
    const float i0 = 1.f / l0, i1 = 1.f / l1;
    const int b = bh >> 4, h = bh & 15;
    #pragma unroll
    for (int ni = 0; ni < 8; ni++) {
        int col = ni * 8 + 2 * tig;
        size_t o0 = ((size_t)(b * SS + row0)) * DD + h * HDIM + col;
        size_t o1 = ((size_t)(b * SS + row1)) * DD + h * HDIM + col;
        *(uint32_t*)&g_AO[o0] = h2(oacc[ni][0] * i0, oacc[ni][1] * i0);
        *(uint32_t*)&g_AO[o1] = h2(oacc[ni][2] * i1, oacc[ni][3] * i1);
    }
}

// ---------------------------------------------------------------------------
extern "C" void kernel_launch(void* const* d_in, const int* in_sizes, int n_in,
                              void* d_out, int out_size)
{
    const float* x  = (const float*)d_in[0];
    const float* fc = (const float*)d_in[1];
    const float* fs = (const float*)d_in[2];
    float* out = (float*)d_out;

    const int gemm_smem = 73728;
    const int attn_smem = 36864;
    cudaFuncSetAttribute(qkv_f16, cudaFuncAttributeMaxDynamicSharedMemorySize, gemm_smem);
    cudaFuncSetAttribute(gemm_o,  cudaFuncAttributeMaxDynamicSharedMemorySize, gemm_smem);
    cudaFuncSetAttribute(attn_f16, cudaFuncAttributeMaxDynamicSharedMemorySize, attn_smem);

    const int ncvt = N4X + 4 * N4W;    // 3145728
    cvt_all<<<ncvt / 256, 256>>>((const float4*)x,
                                 (const float4*)d_in[3], (const float4*)d_in[4],
                                 (const float4*)d_in[5], (const float4*)d_in[6]);

    dim3 gq(DD / 128, MM / 128, 3);    // (8, 64, 3)
    qkv_f16<<<gq, 256, gemm_smem>>>(fc, fs);

    dim3 ag(SS / 128, BB * HH);        // (16, 64)
    attn_f16<<<ag, 256, attn_smem>>>();

    dim3 go(DD / 128, MM / 128);       // (8, 64)
    gemm_o<<<go, 256, gemm_smem>>>(out);
}

// round 12
// speedup vs baseline: 1.4152x; 1.4152x over previous
#include <cuda_runtime.h>
#include <cuda_fp16.h>
#include <stdint.h>

#define BB 4
#define SS 2048
#define DD 1024
#define HH 16
#define HDIM 64
#define MM (BB*SS)   // 8192

// Scratch (allocation-free rule: __device__ globals). All fp16.
__device__ __half g_Xt[(size_t)MM*DD];
__device__ __half g_Wt[(size_t)4*DD*DD];    // wq,wk,wv,wo
__device__ __half g_Q [(size_t)MM*DD];      // [B,H,S,HD]
__device__ __half g_K [(size_t)MM*DD];
__device__ __half g_V [(size_t)MM*DD];      // TRANSPOSED: [B,H,HD,S]
__device__ __half g_AO[(size_t)MM*DD];      // [B,S,D]

__device__ __forceinline__ float ex2(float x) {
    float r;
    asm("ex2.approx.f32 %0, %1;" : "=f"(r) : "f"(x));
    return r;
}
__device__ __forceinline__ uint32_t h2(float a, float b) {
    __half2 h = __floats2half2_rn(a, b);
    return *(uint32_t*)&h;
}
__device__ __forceinline__ void mmaf16(float* c, const uint32_t* a, const uint32_t* b) {
    asm volatile(
        "mma.sync.aligned.m16n8k16.row.col.f32.f16.f16.f32 "
        "{%0,%1,%2,%3},{%4,%5,%6,%7},{%8,%9},{%0,%1,%2,%3};"
        : "+f"(c[0]), "+f"(c[1]), "+f"(c[2]), "+f"(c[3])
        : "r"(a[0]), "r"(a[1]), "r"(a[2]), "r"(a[3]), "r"(b[0]), "r"(b[1]));
}
__device__ __forceinline__ void cpa16(uint32_t dst, const void* src) {
    asm volatile("cp.async.cg.shared.global [%0], [%1], 16;" :: "r"(dst), "l"(src));
}
__device__ __forceinline__ void cpcommit() {
    asm volatile("cp.async.commit_group;");
}
template<int N> __device__ __forceinline__ void cpwait() {
    asm volatile("cp.async.wait_group %0;" :: "n"(N));
}

// ---------------------------------------------------------------------------
// Fused prepass: fp32 -> fp16 (RN) for x + all 4 weights, one launch.
// ---------------------------------------------------------------------------
#define N4X (MM*DD/4)       // 2097152
#define N4W (DD*DD/4)       // 262144 = 2^18
__global__ void cvt_all(const float4* __restrict__ x,
                        const float4* __restrict__ wq, const float4* __restrict__ wk,
                        const float4* __restrict__ wv, const float4* __restrict__ wo) {
    int i = blockIdx.x * 256 + threadIdx.x;
    const float4* src;
    __half* dst;
    int j;
    if (i < N4X) {
        src = x; dst = g_Xt; j = i;
    } else {
        int k = i - N4X;
        int w = k >> 18;
        j = k & (N4W - 1);
        src = (w == 0) ? wq : (w == 1) ? wk : (w == 2) ? wv : wo;
        dst = g_Wt + (size_t)w * DD * DD;
    }
    float4 v = src[j];
    *(uint2*)&dst[(size_t)j * 4] = make_uint2(h2(v.x, v.y), h2(v.z, v.w));
}

// ---------------------------------------------------------------------------
// Shared GEMM mainloop (scalar-LDS fragments — proven faster than ldmatrix
// on sm_103a in R11): acc = A[M,K] @ B[N,K]^T for one 128x128 tile.
// K-slab 64, 2-stage cp.async. Smem halfs: stage s at s*18432; A stride 72,
// B at +9216 halfs.
// ---------------------------------------------------------------------------
__device__ __forceinline__ void g_load(uint32_t smb, int s,
                                       const __half* Ag, const __half* Bg,
                                       int m0, int n0, int k0, int tid) {
    uint32_t sa = smb + (uint32_t)s * 36864u;
    uint32_t sb = sa + 18432u;
    #pragma unroll
    for (int i = 0; i < 4; i++) {
        int c = tid + i * 256;
        int r = c >> 3, cb = (c & 7) * 16;
        cpa16(sa + (uint32_t)(r * 144 + cb), Ag + (size_t)(m0 + r) * DD + k0 + (c & 7) * 8);
    }
    #pragma unroll
    for (int i = 0; i < 4; i++) {
        int c = tid + i * 256;
        int r = c >> 3, cb = (c & 7) * 16;
        cpa16(sb + (uint32_t)(r * 144 + cb), Bg + (size_t)(n0 + r) * DD + k0 + (c & 7) * 8);
    }
    cpcommit();
}

__device__ __forceinline__ void run_gemm(float acc[2][8][4],
                                         const __half* Ag, const __half* Bg,
                                         int m0, int n0, __half* smh, int tid)
{
    const int warp = tid >> 5, lane = tid & 31;
    const int wm = warp & 3, wn = warp >> 2;
    const int g = lane >> 2, tig = lane & 3;
    const uint32_t smb = (uint32_t)__cvta_generic_to_shared(smh);

    g_load(smb, 0, Ag, Bg, m0, n0, 0, tid);

    for (int t = 0; t < 16; t++) {
        const int s = t & 1;
        if (t < 15) {
            g_load(smb, s ^ 1, Ag, Bg, m0, n0, (t + 1) * 64, tid);
            cpwait<1>();
        } else {
            cpwait<0>();
        }
        __syncthreads();

        const __half* As = smh + s * 18432;
        const __half* Bs = As + 9216;
        #pragma unroll
        for (int ks = 0; ks < 4; ks++) {
            uint32_t a[2][4], b[8][2];
            #pragma unroll
            for (int mi = 0; mi < 2; mi++) {
                int cb = (wm * 32 + mi * 16 + g) * 72 + ks * 16 + 2 * tig;
                a[mi][0] = *(const uint32_t*)&As[cb];
                a[mi][1] = *(const uint32_t*)&As[cb + 8 * 72];
                a[mi][2] = *(const uint32_t*)&As[cb + 8];
                a[mi][3] = *(const uint32_t*)&As[cb + 8 * 72 + 8];
            }
            #pragma unroll
            for (int ni = 0; ni < 8; ni++) {
                int cb = (wn * 64 + ni * 8 + g) * 72 + ks * 16 + 2 * tig;
                b[ni][0] = *(const uint32_t*)&Bs[cb];
                b[ni][1] = *(const uint32_t*)&Bs[cb + 8];
            }
            #pragma unroll
            for (int mi = 0; mi < 2; mi++)
                #pragma unroll
                for (int ni = 0; ni < 8; ni++)
                    mmaf16(acc[mi][ni], a[mi], b[ni]);
        }
        __syncthreads();
    }
}

// ---------------------------------------------------------------------------
// Fused QKV projection: z = 0/1/2 -> Q/K (RoPE) / V (transposed write).
// ---------------------------------------------------------------------------
__global__ __launch_bounds__(256, 2)
void qkv_f16(const float* __restrict__ fc, const float* __restrict__ fs)
{
    extern __shared__ __half smh[];
    const int tid = threadIdx.x;
    const int m0 = blockIdx.y * 128, n0 = blockIdx.x * 128;
    const int z = blockIdx.z;
    const int warp = tid >> 5, lane = tid & 31;
    const int wm = warp & 3, wn = warp >> 2;
    const int g = lane >> 2, tig = lane & 3;

    float acc[2][8][4];
    #pragma unroll
    for (int mi = 0; mi < 2; mi++)
        #pragma unroll
        for (int ni = 0; ni < 8; ni++)
            #pragma unroll
            for (int j = 0; j < 4; j++) acc[mi][ni][j] = 0.f;

    run_gemm(acc, g_Xt, g_Wt + (size_t)z * DD * DD, m0, n0, smh, tid);

    #pragma unroll
    for (int mi = 0; mi < 2; mi++) {
        #pragma unroll
        for (int ni = 0; ni < 8; ni++) {
            const int m = m0 + wm * 32 + mi * 16 + g;
            const int n = n0 + wn * 64 + ni * 8 + 2 * tig;
            float c0 = acc[mi][ni][0], c1 = acc[mi][ni][1];
            float c2 = acc[mi][ni][2], c3 = acc[mi][ni][3];
            const int b = m >> 11, sl = m & (SS - 1);
            const int h = n >> 6, d = n & 63;
            const int bh = b * HH + h;
            if (z == 2) {
                size_t ov = ((size_t)bh * HDIM + d) * SS + sl;
                g_V[ov]          = __float2half_rn(c0);
                g_V[ov + SS]     = __float2half_rn(c1);
                g_V[ov + 8]      = __float2half_rn(c2);
                g_V[ov + SS + 8] = __float2half_rn(c3);
            } else {
                const int f = d >> 1;
                float cA = fc[sl * 32 + f],       sA = fs[sl * 32 + f];
                float cB = fc[(sl + 8) * 32 + f], sB = fs[(sl + 8) * 32 + f];
                float v0 = c0 * cA - c1 * sA, v1 = c0 * sA + c1 * cA;
                float v2 = c2 * cB - c3 * sB, v3 = c2 * sB + c3 * cB;
                __half* dstq = (z == 0) ? g_Q : g_K;
                size_t o = ((size_t)bh * SS + sl) * HDIM + d;
                *(uint32_t*)&dstq[o]            = h2(v0, v1);
                *(uint32_t*)&dstq[o + 8 * HDIM] = h2(v2, v3);
            }
        }
    }
}

// ---------------------------------------------------------------------------
// Output projection: g_AO @ wo -> fp32 out.
// ---------------------------------------------------------------------------
__global__ __launch_bounds__(256, 2)
void gemm_o(float* __restrict__ out)
{
    extern __shared__ __half smh[];
    const int tid = threadIdx.x;
    const int m0 = blockIdx.y * 128, n0 = blockIdx.x * 128;
    const int warp = tid >> 5, lane = tid & 31;
    const int wm = warp & 3, wn = warp >> 2;
    const int g = lane >> 2, tig = lane & 3;

    float acc[2][8][4];
    #pragma unroll
    for (int mi = 0; mi < 2; mi++)
        #pragma unroll
        for (int ni = 0; ni < 8; ni++)
            #pragma unroll
            for (int j = 0; j < 4; j++) acc[mi][ni][j] = 0.f;

    run_gemm(acc, g_AO, g_Wt + (size_t)3 * DD * DD, m0, n0, smh, tid);

    #pragma unroll
    for (int mi = 0; mi < 2; mi++) {
        #pragma unroll
        for (int ni = 0; ni < 8; ni++) {
            const int m = m0 + wm * 32 + mi * 16 + g;
            const int n = n0 + wn * 64 + ni * 8 + 2 * tig;
            *(float2*)&out[(size_t)m * DD + n] =
                make_float2(acc[mi][ni][0], acc[mi][ni][1]);
            *(float2*)&out[(size_t)(m + 8) * DD + n] =
                make_float2(acc[mi][ni][2], acc[mi][ni][3]);
        }
    }
}

// ---------------------------------------------------------------------------
// Flash attention fp16 (scalar-LDS fragments). 256 thr = 2 q-groups x 4
// warps; 128 q rows/CTA; 64-key tiles double-buffered; P in registers.
// Smem halfs: Ks[s] at s*4608 (64x72), Vt[s] at 9216 + s*4608. 36864 B.
// ---------------------------------------------------------------------------
__device__ __forceinline__ void attn_load(uint32_t smb, int stage,
                                          const __half* Kg, const __half* Vtg,
                                          int kt, int tid) {
    uint32_t ks = smb + (uint32_t)stage * 9216u;
    uint32_t vs = smb + 18432u + (uint32_t)stage * 9216u;
    #pragma unroll
    for (int i = 0; i < 2; i++) {
        int c = tid + i * 256;
        int r = c >> 3, cb = (c & 7) * 16;
        cpa16(ks + (uint32_t)(r * 144 + cb), Kg + (size_t)(kt * 64 + r) * HDIM + (c & 7) * 8);
        cpa16(vs + (uint32_t)(r * 144 + cb), Vtg + (size_t)r * SS + kt * 64 + (c & 7) * 8);
    }
}

#define SCL 0.18033688f   // 0.125 * log2(e)

__global__ __launch_bounds__(256, 2)
void attn_f16()
{
    extern __shared__ __half smh[];
    const int tid = threadIdx.x, warp = tid >> 5, lane = tid & 31;
    const int g = lane >> 2, tig = lane & 3;
    const int gid = warp >> 2, w4 = warp & 3;
    const int qb = gridDim.x - 1 - blockIdx.x;   // heaviest tiles first
    const int bh = blockIdx.y;
    const size_t base = (size_t)bh * SS * HDIM;
    const int mylim = 2 * qb + gid;
    const int lim = 2 * qb + 1;
    const int row0 = qb * 128 + gid * 64 + w4 * 16 + g;
    const int row1 = row0 + 8;
    const uint32_t smb = (uint32_t)__cvta_generic_to_shared(smh);

    // Q fragments direct from gmem (fp16). aq[kk] covers dims 16kk..16kk+15.
    uint32_t aq[4][4];
    {
        const __half* Q0 = g_Q + base + (size_t)row0 * HDIM;
        #pragma unroll
        for (int kk = 0; kk < 4; kk++) {
            int c = kk * 16 + 2 * tig;
            aq[kk][0] = *(const uint32_t*)&Q0[c];
            aq[kk][1] = *(const uint32_t*)&Q0[8 * HDIM + c];
            aq[kk][2] = *(const uint32_t*)&Q0[c + 8];
            aq[kk][3] = *(const uint32_t*)&Q0[8 * HDIM + c + 8];
        }
    }

    float oacc[8][4];
    #pragma unroll
    for (int ni = 0; ni < 8; ni++)
        #pragma unroll
        for (int j = 0; j < 4; j++) oacc[ni][j] = 0.f;
    float m0 = -1e30f, m1 = -1e30f, l0 = 0.f, l1 = 0.f;

    const __half* Kg  = g_K + base;
    const __half* Vtg = g_V + base;

    attn_load(smb, 0, Kg, Vtg, 0, tid);
    cpcommit();

    for (int kt = 0; kt <= lim; kt++) {
        const int s = kt & 1;
        if (kt < lim) {
            attn_load(smb, s ^ 1, Kg, Vtg, kt + 1, tid);
            cpcommit();
            cpwait<1>();
        } else {
            cpwait<0>();
        }
        __syncthreads();

        if (kt <= mylim) {
            const __half* Ks = smh + s * 4608;
            const __half* Vt = smh + 9216 + s * 4608;

            // S = Q @ K^T  (keys = n, dims = k)
            float sc[8][4];
            #pragma unroll
            for (int ni = 0; ni < 8; ni++)
                #pragma unroll
                for (int j = 0; j < 4; j++) sc[ni][j] = 0.f;
            #pragma unroll
            for (int kk = 0; kk < 4; kk++) {
                uint32_t b[8][2];
                #pragma unroll
                for (int ni = 0; ni < 8; ni++) {
                    int cb = (ni * 8 + g) * 72 + kk * 16 + 2 * tig;
                    b[ni][0] = *(const uint32_t*)&Ks[cb];
                    b[ni][1] = *(const uint32_t*)&Ks[cb + 8];
                }
                #pragma unroll
                for (int ni = 0; ni < 8; ni++) mmaf16(sc[ni], aq[kk], b[ni]);
            }

            // scale (log2 domain) + causal mask on diagonal tile + row max
            const bool diag = (kt == mylim);
            float nm0 = m0, nm1 = m1;
            #pragma unroll
            for (int ni = 0; ni < 8; ni++) {
                int col = kt * 64 + ni * 8 + 2 * tig;
                #pragma unroll
                for (int j = 0; j < 4; j++) sc[ni][j] *= SCL;
                if (diag) {
                    if (col     > row0) sc[ni][0] = -1e30f;
                    if (col + 1 > row0) sc[ni][1] = -1e30f;
                    if (col     > row1) sc[ni][2] = -1e30f;
                    if (col + 1 > row1) sc[ni][3] = -1e30f;
                }
                nm0 = fmaxf(nm0, fmaxf(sc[ni][0], sc[ni][1]));
                nm1 = fmaxf(nm1, fmaxf(sc[ni][2], sc[ni][3]));
            }
            nm0 = fmaxf(nm0, __shfl_xor_sync(0xffffffffu, nm0, 1));
            nm0 = fmaxf(nm0, __shfl_xor_sync(0xffffffffu, nm0, 2));
            nm1 = fmaxf(nm1, __shfl_xor_sync(0xffffffffu, nm1, 1));
            nm1 = fmaxf(nm1, __shfl_xor_sync(0xffffffffu, nm1, 2));
            const float corr0 = ex2(m0 - nm0), corr1 = ex2(m1 - nm1);
            m0 = nm0; m1 = nm1;

            // exp; P stays in registers (fp16 C->A fragment identity)
            float ps[8][4];
            float ls0 = 0.f, ls1 = 0.f;
            #pragma unroll
            for (int ni = 0; ni < 8; ni++) {
                ps[ni][0] = ex2(sc[ni][0] - m0);
                ps[ni][1] = ex2(sc[ni][1] - m0);
                ps[ni][2] = ex2(sc[ni][2] - m1);
                ps[ni][3] = ex2(sc[ni][3] - m1);
                ls0 += ps[ni][0] + ps[ni][1];
                ls1 += ps[ni][2] + ps[ni][3];
            }
            l0 = l0 * corr0 + ls0;
            l1 = l1 * corr1 + ls1;
            #pragma unroll
            for (int ni = 0; ni < 8; ni++) {
                oacc[ni][0] *= corr0; oacc[ni][1] *= corr0;
                oacc[ni][2] *= corr1; oacc[ni][3] *= corr1;
            }

            // O += P @ V  (dims = n via Vt rows, keys = k)
            #pragma unroll
            for (int kk = 0; kk < 4; kk++) {
                uint32_t pa[4];
                pa[0] = h2(ps[2*kk][0],   ps[2*kk][1]);
                pa[1] = h2(ps[2*kk][2],   ps[2*kk][3]);
                pa[2] = h2(ps[2*kk+1][0], ps[2*kk+1][1]);
                pa[3] = h2(ps[2*kk+1][2], ps[2*kk+1][3]);
                uint32_t b[8][2];
                #pragma unroll
                for (int ni = 0; ni < 8; ni++) {
                    int cb = (ni * 8 + g) * 72 + kk * 16 + 2 * tig;
                    b[ni][0] = *(const uint32_t*)&Vt[cb];
                    b[ni][1] = *(const uint32_t*)&Vt[cb + 8];
                }
                #pragma unroll
                for (int ni = 0; ni < 8; ni++) mmaf16(oacc[ni], pa, b[ni]);
            }
        }
        __syncthreads();
    }

    // Finalize
    l0 += __shfl_xor_sync(0xffffffffu, l0, 1);
    l0 += __shfl_xor_sync(0xffffffffu, l0, 2);
    l1 += __shfl_xor_sync(0xffffffffu, l1, 1);
    l1 += __shfl_xor_sync(0xffffffffu, l1, 2);
    const float i0 = 1.f / l0, i1 = 1.f / l1;
    const int b = bh >> 4, h = bh & 15;
    #pragma unroll
    for (int ni = 0; ni < 8; ni++) {
        int col = ni * 8 + 2 * tig;
        size_t o0 = ((size_t)(b * SS + row0)) * DD + h * HDIM + col;
        size_t o1 = ((size_t)(b * SS + row1)) * DD + h * HDIM + col;
        *(uint32_t*)&g_AO[o0] = h2(oacc[ni][0] * i0, oacc[ni][1] * i0);
        *(uint32_t*)&g_AO[o1] = h2(oacc[ni][2] * i1, oacc[ni][3] * i1);
    }
}

// ---------------------------------------------------------------------------
extern "C" void kernel_launch(void* const* d_in, const int* in_sizes, int n_in,
                              void* d_out, int out_size)
{
    const float* x  = (const float*)d_in[0];
    const float* fc = (const float*)d_in[1];
    const float* fs = (const float*)d_in[2];
    float* out = (float*)d_out;

    const int gemm_smem = 73728;
    const int attn_smem = 36864;
    cudaFuncSetAttribute(qkv_f16, cudaFuncAttributeMaxDynamicSharedMemorySize, gemm_smem);
    cudaFuncSetAttribute(gemm_o,  cudaFuncAttributeMaxDynamicSharedMemorySize, gemm_smem);
    cudaFuncSetAttribute(attn_f16, cudaFuncAttributeMaxDynamicSharedMemorySize, attn_smem);

    const int ncvt = N4X + 4 * N4W;    // 3145728
    cvt_all<<<ncvt / 256, 256>>>((const float4*)x,
                                 (const float4*)d_in[3], (const float4*)d_in[4],
                                 (const float4*)d_in[5], (const float4*)d_in[6]);

    dim3 gq(DD / 128, MM / 128, 3);    // (8, 64, 3)
    qkv_f16<<<gq, 256, gemm_smem>>>(fc, fs);

    dim3 ag(SS / 128, BB * HH);        // (16, 64)
    attn_f16<<<ag, 256, attn_smem>>>();

    dim3 go(DD / 128, MM / 128);       // (8, 64)
    gemm_o<<<go, 256, gemm_smem>>>(out);
}

// round 13
// speedup vs baseline: 1.4237x; 1.0060x over previous
#include <cuda_runtime.h>
#include <cuda_fp16.h>
#include <stdint.h>

#define BB 4
#define SS 2048
#define DD 1024
#define HH 16
#define HDIM 64
#define MM (BB*SS)   // 8192

// Scratch (allocation-free rule: __device__ globals). All fp16.
__device__ __half g_Xt[(size_t)MM*DD];
__device__ __half g_Wt[(size_t)4*DD*DD];    // wq,wk,wv,wo
__device__ __half g_Q [(size_t)MM*DD];      // [B,H,S,HD]
__device__ __half g_K [(size_t)MM*DD];
__device__ __half g_V [(size_t)MM*DD];      // TRANSPOSED: [B,H,HD,S]
__device__ __half g_AO[(size_t)MM*DD];      // [B,S,D]

__device__ __forceinline__ float ex2(float x) {
    float r;
    asm("ex2.approx.f32 %0, %1;" : "=f"(r) : "f"(x));
    return r;
}
__device__ __forceinline__ uint32_t h2(float a, float b) {
    __half2 h = __floats2half2_rn(a, b);
    return *(uint32_t*)&h;
}
__device__ __forceinline__ void mmaf16(float* c, const uint32_t* a, const uint32_t* b) {
    asm volatile(
        "mma.sync.aligned.m16n8k16.row.col.f32.f16.f16.f32 "
        "{%0,%1,%2,%3},{%4,%5,%6,%7},{%8,%9},{%0,%1,%2,%3};"
        : "+f"(c[0]), "+f"(c[1]), "+f"(c[2]), "+f"(c[3])
        : "r"(a[0]), "r"(a[1]), "r"(a[2]), "r"(a[3]), "r"(b[0]), "r"(b[1]));
}
__device__ __forceinline__ void cpa16(uint32_t dst, const void* src) {
    asm volatile("cp.async.cg.shared.global [%0], [%1], 16;" :: "r"(dst), "l"(src));
}
__device__ __forceinline__ void cpcommit() {
    asm volatile("cp.async.commit_group;");
}
template<int N> __device__ __forceinline__ void cpwait() {
    asm volatile("cp.async.wait_group %0;" :: "n"(N));
}

// ---------------------------------------------------------------------------
// Fused prepass: fp32 -> fp16 (RN) for x + all 4 weights, one launch.
// ---------------------------------------------------------------------------
#define N4X (MM*DD/4)       // 2097152
#define N4W (DD*DD/4)       // 262144 = 2^18
__global__ void cvt_all(const float4* __restrict__ x,
                        const float4* __restrict__ wq, const float4* __restrict__ wk,
                        const float4* __restrict__ wv, const float4* __restrict__ wo) {
    int i = blockIdx.x * 256 + threadIdx.x;
    const float4* src;
    __half* dst;
    int j;
    if (i < N4X) {
        src = x; dst = g_Xt; j = i;
    } else {
        int k = i - N4X;
        int w = k >> 18;
        j = k & (N4W - 1);
        src = (w == 0) ? wq : (w == 1) ? wk : (w == 2) ? wv : wo;
        dst = g_Wt + (size_t)w * DD * DD;
    }
    float4 v = src[j];
    *(uint2*)&dst[(size_t)j * 4] = make_uint2(h2(v.x, v.y), h2(v.z, v.w));
}

// ---------------------------------------------------------------------------
// Shared GEMM mainloop: acc = A[M,K] @ B[N,K]^T for one 128x128 tile.
// K-slab 64, 3-stage cp.async, ONE barrier per iteration (multistage).
// Smem halfs: stage s at s*18432; A stride 72, B at +9216 halfs.
// Scalar-LDS fragments (proven faster than ldmatrix on sm_103a, R11).
// ---------------------------------------------------------------------------
__device__ __forceinline__ void g_load(uint32_t smb, int s,
                                       const __half* Ag, const __half* Bg,
                                       int m0, int n0, int k0, int tid) {
    uint32_t sa = smb + (uint32_t)s * 36864u;
    uint32_t sb = sa + 18432u;
    #pragma unroll
    for (int i = 0; i < 4; i++) {
        int c = tid + i * 256;
        int r = c >> 3, cb = (c & 7) * 16;
        cpa16(sa + (uint32_t)(r * 144 + cb), Ag + (size_t)(m0 + r) * DD + k0 + (c & 7) * 8);
    }
    #pragma unroll
    for (int i = 0; i < 4; i++) {
        int c = tid + i * 256;
        int r = c >> 3, cb = (c & 7) * 16;
        cpa16(sb + (uint32_t)(r * 144 + cb), Bg + (size_t)(n0 + r) * DD + k0 + (c & 7) * 8);
    }
    cpcommit();
}

__device__ __forceinline__ void run_gemm(float acc[2][8][4],
                                         const __half* Ag, const __half* Bg,
                                         int m0, int n0, __half* smh, int tid)
{
    const int warp = tid >> 5, lane = tid & 31;
    const int wm = warp & 3, wn = warp >> 2;
    const int g = lane >> 2, tig = lane & 3;
    const uint32_t smb = (uint32_t)__cvta_generic_to_shared(smh);

    g_load(smb, 0, Ag, Bg, m0, n0, 0,  tid);
    g_load(smb, 1, Ag, Bg, m0, n0, 64, tid);

    for (int t = 0; t < 16; t++) {
        if (t < 15) cpwait<1>(); else cpwait<0>();
        __syncthreads();
        if (t + 2 < 16)
            g_load(smb, (t + 2) % 3, Ag, Bg, m0, n0, (t + 2) * 64, tid);

        const __half* As = smh + (t % 3) * 18432;
        const __half* Bs = As + 9216;
        #pragma unroll
        for (int ks = 0; ks < 4; ks++) {
            uint32_t a[2][4], b[8][2];
            #pragma unroll
            for (int mi = 0; mi < 2; mi++) {
                int cb = (wm * 32 + mi * 16 + g) * 72 + ks * 16 + 2 * tig;
                a[mi][0] = *(const uint32_t*)&As[cb];
                a[mi][1] = *(const uint32_t*)&As[cb + 8 * 72];
                a[mi][2] = *(const uint32_t*)&As[cb + 8];
                a[mi][3] = *(const uint32_t*)&As[cb + 8 * 72 + 8];
            }
            #pragma unroll
            for (int ni = 0; ni < 8; ni++) {
                int cb = (wn * 64 + ni * 8 + g) * 72 + ks * 16 + 2 * tig;
                b[ni][0] = *(const uint32_t*)&Bs[cb];
                b[ni][1] = *(const uint32_t*)&Bs[cb + 8];
            }
            #pragma unroll
            for (int mi = 0; mi < 2; mi++)
                #pragma unroll
                for (int ni = 0; ni < 8; ni++)
                    mmaf16(acc[mi][ni], a[mi], b[ni]);
        }
    }
}

// ---------------------------------------------------------------------------
// Fused QKV projection: z = 0/1/2 -> Q/K (RoPE) / V (transposed write).
// ---------------------------------------------------------------------------
__global__ __launch_bounds__(256, 2)
void qkv_f16(const float* __restrict__ fc, const float* __restrict__ fs)
{
    extern __shared__ __half smh[];
    const int tid = threadIdx.x;
    const int m0 = blockIdx.y * 128, n0 = blockIdx.x * 128;
    const int z = blockIdx.z;
    const int warp = tid >> 5, lane = tid & 31;
    const int wm = warp & 3, wn = warp >> 2;
    const int g = lane >> 2, tig = lane & 3;

    float acc[2][8][4];
    #pragma unroll
    for (int mi = 0; mi < 2; mi++)
        #pragma unroll
        for (int ni = 0; ni < 8; ni++)
            #pragma unroll
            for (int j = 0; j < 4; j++) acc[mi][ni][j] = 0.f;

    run_gemm(acc, g_Xt, g_Wt + (size_t)z * DD * DD, m0, n0, smh, tid);

    #pragma unroll
    for (int mi = 0; mi < 2; mi++) {
        #pragma unroll
        for (int ni = 0; ni < 8; ni++) {
            const int m = m0 + wm * 32 + mi * 16 + g;
            const int n = n0 + wn * 64 + ni * 8 + 2 * tig;
            float c0 = acc[mi][ni][0], c1 = acc[mi][ni][1];
            float c2 = acc[mi][ni][2], c3 = acc[mi][ni][3];
            const int b = m >> 11, sl = m & (SS - 1);
            const int h = n >> 6, d = n & 63;
            const int bh = b * HH + h;
            if (z == 2) {
                size_t ov = ((size_t)bh * HDIM + d) * SS + sl;
                g_V[ov]          = __float2half_rn(c0);
                g_V[ov + SS]     = __float2half_rn(c1);
                g_V[ov + 8]      = __float2half_rn(c2);
                g_V[ov + SS + 8] = __float2half_rn(c3);
            } else {
                const int f = d >> 1;
                float cA = fc[sl * 32 + f],       sA = fs[sl * 32 + f];
                float cB = fc[(sl + 8) * 32 + f], sB = fs[(sl + 8) * 32 + f];
                float v0 = c0 * cA - c1 * sA, v1 = c0 * sA + c1 * cA;
                float v2 = c2 * cB - c3 * sB, v3 = c2 * sB + c3 * cB;
                __half* dstq = (z == 0) ? g_Q : g_K;
                size_t o = ((size_t)bh * SS + sl) * HDIM + d;
                *(uint32_t*)&dstq[o]            = h2(v0, v1);
                *(uint32_t*)&dstq[o + 8 * HDIM] = h2(v2, v3);
            }
        }
    }
}

// ---------------------------------------------------------------------------
// Output projection: g_AO @ wo -> fp32 out.
// ---------------------------------------------------------------------------
__global__ __launch_bounds__(256, 2)
void gemm_o(float* __restrict__ out)
{
    extern __shared__ __half smh[];
    const int tid = threadIdx.x;
    const int m0 = blockIdx.y * 128, n0 = blockIdx.x * 128;
    const int warp = tid >> 5, lane = tid & 31;
    const int wm = warp & 3, wn = warp >> 2;
    const int g = lane >> 2, tig = lane & 3;

    float acc[2][8][4];
    #pragma unroll
    for (int mi = 0; mi < 2; mi++)
        #pragma unroll
        for (int ni = 0; ni < 8; ni++)
            #pragma unroll
            for (int j = 0; j < 4; j++) acc[mi][ni][j] = 0.f;

    run_gemm(acc, g_AO, g_Wt + (size_t)3 * DD * DD, m0, n0, smh, tid);

    #pragma unroll
    for (int mi = 0; mi < 2; mi++) {
        #pragma unroll
        for (int ni = 0; ni < 8; ni++) {
            const int m = m0 + wm * 32 + mi * 16 + g;
            const int n = n0 + wn * 64 + ni * 8 + 2 * tig;
            *(float2*)&out[(size_t)m * DD + n] =
                make_float2(acc[mi][ni][0], acc[mi][ni][1]);
            *(float2*)&out[(size_t)(m + 8) * DD + n] =
                make_float2(acc[mi][ni][2], acc[mi][ni][3]);
        }
    }
}

// ---------------------------------------------------------------------------
// Flash attention fp16. 256 thr = 2 q-groups x 4 warps; 128 q rows/CTA;
// 64-key tiles, 3-stage cp.async, ONE barrier per iteration; P in registers.
// Smem: stage s at s*18432 B (K 9216 B + Vt 9216 B). Total 55296 B.
// ---------------------------------------------------------------------------
__device__ __forceinline__ void attn_load(uint32_t smb, int stage,
                                          const __half* Kg, const __half* Vtg,
                                          int kt, int tid) {
    uint32_t ks = smb + (uint32_t)stage * 18432u;
    uint32_t vs = ks + 9216u;
    #pragma unroll
    for (int i = 0; i < 2; i++) {
        int c = tid + i * 256;
        int r = c >> 3, cb = (c & 7) * 16;
        cpa16(ks + (uint32_t)(r * 144 + cb), Kg + (size_t)(kt * 64 + r) * HDIM + (c & 7) * 8);
        cpa16(vs + (uint32_t)(r * 144 + cb), Vtg + (size_t)r * SS + kt * 64 + (c & 7) * 8);
    }
    cpcommit();
}

#define SCL 0.18033688f   // 0.125 * log2(e)

__global__ __launch_bounds__(256, 2)
void attn_f16()
{
    extern __shared__ __half smh[];
    const int tid = threadIdx.x, warp = tid >> 5, lane = tid & 31;
    const int g = lane >> 2, tig = lane & 3;
    const int gid = warp >> 2, w4 = warp & 3;
    const int qb = gridDim.x - 1 - blockIdx.x;   // heaviest tiles first
    const int bh = blockIdx.y;
    const size_t base = (size_t)bh * SS * HDIM;
    const int mylim = 2 * qb + gid;
    const int lim = 2 * qb + 1;
    const int row0 = qb * 128 + gid * 64 + w4 * 16 + g;
    const int row1 = row0 + 8;
    const uint32_t smb = (uint32_t)__cvta_generic_to_shared(smh);

    // Q fragments direct from gmem (fp16). aq[kk] covers dims 16kk..16kk+15.
    uint32_t aq[4][4];
    {
        const __half* Q0 = g_Q + base + (size_t)row0 * HDIM;
        #pragma unroll
        for (int kk = 0; kk < 4; kk++) {
            int c = kk * 16 + 2 * tig;
            aq[kk][0] = *(const uint32_t*)&Q0[c];
            aq[kk][1] = *(const uint32_t*)&Q0[8 * HDIM + c];
            aq[kk][2] = *(const uint32_t*)&Q0[c + 8];
            aq[kk][3] = *(const uint32_t*)&Q0[8 * HDIM + c + 8];
        }
    }

    float oacc[8][4];
    #pragma unroll
    for (int ni = 0; ni < 8; ni++)
        #pragma unroll
        for (int j = 0; j < 4; j++) oacc[ni][j] = 0.f;
    float m0 = -1e30f, m1 = -1e30f, l0 = 0.f, l1 = 0.f;

    const __half* Kg  = g_K + base;
    const __half* Vtg = g_V + base;

    attn_load(smb, 0, Kg, Vtg, 0, tid);
    attn_load(smb, 1, Kg, Vtg, 1, tid);

    for (int kt = 0; kt <= lim; kt++) {
        if (kt < lim) cpwait<1>(); else cpwait<0>();
        __syncthreads();
        if (kt + 2 <= lim)
            attn_load(smb, (kt + 2) % 3, Kg, Vtg, kt + 2, tid);

        if (kt <= mylim) {
            const __half* Ks = smh + (kt % 3) * 9216;
            const __half* Vt = Ks + 4608;

            // S = Q @ K^T  (keys = n, dims = k)
            float sc[8][4];
            #pragma unroll
            for (int ni = 0; ni < 8; ni++)
                #pragma unroll
                for (int j = 0; j < 4; j++) sc[ni][j] = 0.f;
            #pragma unroll
            for (int kk = 0; kk < 4; kk++) {
                uint32_t b[8][2];
                #pragma unroll
                for (int ni = 0; ni < 8; ni++) {
                    int cb = (ni * 8 + g) * 72 + kk * 16 + 2 * tig;
                    b[ni][0] = *(const uint32_t*)&Ks[cb];
                    b[ni][1] = *(const uint32_t*)&Ks[cb + 8];
                }
                #pragma unroll
                for (int ni = 0; ni < 8; ni++) mmaf16(sc[ni], aq[kk], b[ni]);
            }

            // scale (log2 domain) + causal mask on diagonal tile + row max
            const bool diag = (kt == mylim);
            float nm0 = m0, nm1 = m1;
            #pragma unroll
            for (int ni = 0; ni < 8; ni++) {
                int col = kt * 64 + ni * 8 + 2 * tig;
                #pragma unroll
                for (int j = 0; j < 4; j++) sc[ni][j] *= SCL;
                if (diag) {
                    if (col     > row0) sc[ni][0] = -1e30f;
                    if (col + 1 > row0) sc[ni][1] = -1e30f;
                    if (col     > row1) sc[ni][2] = -1e30f;
                    if (col + 1 > row1) sc[ni][3] = -1e30f;
                }
                nm0 = fmaxf(nm0, fmaxf(sc[ni][0], sc[ni][1]));
                nm1 = fmaxf(nm1, fmaxf(sc[ni][2], sc[ni][3]));
            }
            nm0 = fmaxf(nm0, __shfl_xor_sync(0xffffffffu, nm0, 1));
            nm0 = fmaxf(nm0, __shfl_xor_sync(0xffffffffu, nm0, 2));
            nm1 = fmaxf(nm1, __shfl_xor_sync(0xffffffffu, nm1, 1));
            nm1 = fmaxf(nm1, __shfl_xor_sync(0xffffffffu, nm1, 2));
            const float corr0 = ex2(m0 - nm0), corr1 = ex2(m1 - nm1);
            m0 = nm0; m1 = nm1;

            // exp; P stays in registers (fp16 C->A fragment identity)
            float ps[8][4];
            float ls0 = 0.f, ls1 = 0.f;
            #pragma unroll
            for (int ni = 0; ni < 8; ni++) {
                ps[ni][0] = ex2(sc[ni][0] - m0);
                ps[ni][1] = ex2(sc[ni][1] - m0);
                ps[ni][2] = ex2(sc[ni][2] - m1);
                ps[ni][3] = ex2(sc[ni][3] - m1);
                ls0 += ps[ni][0] + ps[ni][1];
                ls1 += ps[ni][2] + ps[ni][3];
            }
            l0 = l0 * corr0 + ls0;
            l1 = l1 * corr1 + ls1;
            #pragma unroll
            for (int ni = 0; ni < 8; ni++) {
                oacc[ni][0] *= corr0; oacc[ni][1] *= corr0;
                oacc[ni][2] *= corr1; oacc[ni][3] *= corr1;
            }

            // O += P @ V  (dims = n via Vt rows, keys = k)
            #pragma unroll
            for (int kk = 0; kk < 4; kk++) {
                uint32_t pa[4];
                pa[0] = h2(ps[2*kk][0],   ps[2*kk][1]);
                pa[1] = h2(ps[2*kk][2],   ps[2*kk][3]);
                pa[2] = h2(ps[2*kk+1][0], ps[2*kk+1][1]);
                pa[3] = h2(ps[2*kk+1][2], ps[2*kk+1][3]);
                uint32_t b[8][2];
                #pragma unroll
                for (int ni = 0; ni < 8; ni++) {
                    int cb = (ni * 8 + g) * 72 + kk * 16 + 2 * tig;
                    b[ni][0] = *(const uint32_t*)&Vt[cb];
                    b[ni][1] = *(const uint32_t*)&Vt[cb + 8];
                }
                #pragma unroll
                for (int ni = 0; ni < 8; ni++) mmaf16(oacc[ni], pa, b[ni]);
            }
        }
    }

    // Finalize
    l0 += __shfl_xor_sync(0xffffffffu, l0, 1);
    l0 += __shfl_xor_sync(0xffffffffu, l0, 2);
    l1 += __shfl_xor_sync(0xffffffffu, l1, 1);
    l1 += __shfl_xor_sync(0xffffffffu, l1, 2);
    const float i0 = 1.f / l0, i1 = 1.f / l1;
    const int b = bh >> 4, h = bh & 15;
    #pragma unroll
    for (int ni = 0; ni < 8; ni++) {
        int col = ni * 8 + 2 * tig;
        size_t o0 = ((size_t)(b * SS + row0)) * DD + h * HDIM + col;
        size_t o1 = ((size_t)(b * SS + row1)) * DD + h * HDIM + col;
        *(uint32_t*)&g_AO[o0] = h2(oacc[ni][0] * i0, oacc[ni][1] * i0);
        *(uint32_t*)&g_AO[o1] = h2(oacc[ni][2] * i1, oacc[ni][3] * i1);
    }
}

// ---------------------------------------------------------------------------
extern "C" void kernel_launch(void* const* d_in, const int* in_sizes, int n_in,
                              void* d_out, int out_size)
{
    const float* x  = (const float*)d_in[0];
    const float* fc = (const float*)d_in[1];
    const float* fs = (const float*)d_in[2];
    float* out = (float*)d_out;

    const int gemm_smem = 3 * 36864;   // 110592
    const int attn_smem = 3 * 18432;   // 55296
    cudaFuncSetAttribute(qkv_f16, cudaFuncAttributeMaxDynamicSharedMemorySize, gemm_smem);
    cudaFuncSetAttribute(gemm_o,  cudaFuncAttributeMaxDynamicSharedMemorySize, gemm_smem);
    cudaFuncSetAttribute(attn_f16, cudaFuncAttributeMaxDynamicSharedMemorySize, attn_smem);

    const int ncvt = N4X + 4 * N4W;    // 3145728
    cvt_all<<<ncvt / 256, 256>>>((const float4*)x,
                                 (const float4*)d_in[3], (const float4*)d_in[4],
                                 (const float4*)d_in[5], (const float4*)d_in[6]);

    dim3 gq(DD / 128, MM / 128, 3);    // (8, 64, 3)
    qkv_f16<<<gq, 256, gemm_smem>>>(fc, fs);

    dim3 ag(SS / 128, BB * HH);        // (16, 64)
    attn_f16<<<ag, 256, attn_smem>>>();

    dim3 go(DD / 128, MM / 128);       // (8, 64)
    gemm_o<<<go, 256, gemm_smem>>>(out);
}

// round 14
// speedup vs baseline: 1.4636x; 1.0280x over previous
#include <cuda_runtime.h>
#include <cuda_fp16.h>
#include <stdint.h>

#define BB 4
#define SS 2048
#define DD 1024
#define HH 16
#define HDIM 64
#define MM (BB*SS)   // 8192

// Scratch (allocation-free rule: __device__ globals). All fp16.
__device__ __half g_Xt[(size_t)MM*DD];
__device__ __half g_Wt[(size_t)4*DD*DD];    // wq,wk,wv,wo
__device__ __half g_Q [(size_t)MM*DD];      // [B,H,S,HD]
__device__ __half g_K [(size_t)MM*DD];
__device__ __half g_V [(size_t)MM*DD];      // TRANSPOSED: [B,H,HD,S]
__device__ __half g_AO[(size_t)MM*DD];      // [B,S,D]

__device__ __forceinline__ float ex2(float x) {
    float r;
    asm("ex2.approx.f32 %0, %1;" : "=f"(r) : "f"(x));
    return r;
}
__device__ __forceinline__ uint32_t h2(float a, float b) {
    __half2 h = __floats2half2_rn(a, b);
    return *(uint32_t*)&h;
}
__device__ __forceinline__ void mmaf16(float* c, const uint32_t* a, const uint32_t* b) {
    asm volatile(
        "mma.sync.aligned.m16n8k16.row.col.f32.f16.f16.f32 "
        "{%0,%1,%2,%3},{%4,%5,%6,%7},{%8,%9},{%0,%1,%2,%3};"
        : "+f"(c[0]), "+f"(c[1]), "+f"(c[2]), "+f"(c[3])
        : "r"(a[0]), "r"(a[1]), "r"(a[2]), "r"(a[3]), "r"(b[0]), "r"(b[1]));
}
__device__ __forceinline__ void cpa16(uint32_t dst, const void* src) {
    asm volatile("cp.async.cg.shared.global [%0], [%1], 16;" :: "r"(dst), "l"(src));
}
__device__ __forceinline__ void cpcommit() {
    asm volatile("cp.async.commit_group;");
}
template<int N> __device__ __forceinline__ void cpwait() {
    asm volatile("cp.async.wait_group %0;" :: "n"(N));
}

// ---------------------------------------------------------------------------
// Fused prepass: fp32 -> fp16 (RN), ILP=2.
// ---------------------------------------------------------------------------
#define N4X (MM*DD/4)       // 2097152
#define N4W (DD*DD/4)       // 262144 = 2^18
__device__ __forceinline__ void cvt_one(int i,
        const float4* x, const float4* wq, const float4* wk,
        const float4* wv, const float4* wo) {
    const float4* src;
    __half* dst;
    int j;
    if (i < N4X) {
        src = x; dst = g_Xt; j = i;
    } else {
        int k = i - N4X;
        int w = k >> 18;
        j = k & (N4W - 1);
        src = (w == 0) ? wq : (w == 1) ? wk : (w == 2) ? wv : wo;
        dst = g_Wt + (size_t)w * DD * DD;
    }
    float4 v = src[j];
    *(uint2*)&dst[(size_t)j * 4] = make_uint2(h2(v.x, v.y), h2(v.z, v.w));
}
__global__ void cvt_all(const float4* __restrict__ x,
                        const float4* __restrict__ wq, const float4* __restrict__ wk,
                        const float4* __restrict__ wv, const float4* __restrict__ wo) {
    int i = blockIdx.x * 512 + threadIdx.x;
    cvt_one(i, x, wq, wk, wv, wo);
    cvt_one(i + 256, x, wq, wk, wv, wo);
}

// ---------------------------------------------------------------------------
// Shared GEMM mainloop: acc = A[M,K] @ B[N,K]^T for one 128x128 tile.
// K-slab 64, 3-stage cp.async, one barrier per iteration. Scalar-LDS frags.
// ---------------------------------------------------------------------------
__device__ __forceinline__ void g_load(uint32_t smb, int s,
                                       const __half* Ag, const __half* Bg,
                                       int m0, int n0, int k0, int tid) {
    uint32_t sa = smb + (uint32_t)s * 36864u;
    uint32_t sb = sa + 18432u;
    #pragma unroll
    for (int i = 0; i < 4; i++) {
        int c = tid + i * 256;
        int r = c >> 3, cb = (c & 7) * 16;
        cpa16(sa + (uint32_t)(r * 144 + cb), Ag + (size_t)(m0 + r) * DD + k0 + (c & 7) * 8);
    }
    #pragma unroll
    for (int i = 0; i < 4; i++) {
        int c = tid + i * 256;
        int r = c >> 3, cb = (c & 7) * 16;
        cpa16(sb + (uint32_t)(r * 144 + cb), Bg + (size_t)(n0 + r) * DD + k0 + (c & 7) * 8);
    }
    cpcommit();
}

__device__ __forceinline__ void run_gemm(float acc[2][8][4],
                                         const __half* Ag, const __half* Bg,
                                         int m0, int n0, __half* smh, int tid)
{
    const int warp = tid >> 5, lane = tid & 31;
    const int wm = warp & 3, wn = warp >> 2;
    const int g = lane >> 2, tig = lane & 3;
    const uint32_t smb = (uint32_t)__cvta_generic_to_shared(smh);

    g_load(smb, 0, Ag, Bg, m0, n0, 0,  tid);
    g_load(smb, 1, Ag, Bg, m0, n0, 64, tid);

    for (int t = 0; t < 16; t++) {
        if (t < 15) cpwait<1>(); else cpwait<0>();
        __syncthreads();
        if (t + 2 < 16)
            g_load(smb, (t + 2) % 3, Ag, Bg, m0, n0, (t + 2) * 64, tid);

        const __half* As = smh + (t % 3) * 18432;
        const __half* Bs = As + 9216;
        #pragma unroll
        for (int ks = 0; ks < 4; ks++) {
            uint32_t a[2][4], b[8][2];
            #pragma unroll
            for (int mi = 0; mi < 2; mi++) {
                int cb = (wm * 32 + mi * 16 + g) * 72 + ks * 16 + 2 * tig;
                a[mi][0] = *(const uint32_t*)&As[cb];
                a[mi][1] = *(const uint32_t*)&As[cb + 8 * 72];
                a[mi][2] = *(const uint32_t*)&As[cb + 8];
                a[mi][3] = *(const uint32_t*)&As[cb + 8 * 72 + 8];
            }
            #pragma unroll
            for (int ni = 0; ni < 8; ni++) {
                int cb = (wn * 64 + ni * 8 + g) * 72 + ks * 16 + 2 * tig;
                b[ni][0] = *(const uint32_t*)&Bs[cb];
                b[ni][1] = *(const uint32_t*)&Bs[cb + 8];
            }
            #pragma unroll
            for (int mi = 0; mi < 2; mi++)
                #pragma unroll
                for (int ni = 0; ni < 8; ni++)
                    mmaf16(acc[mi][ni], a[mi], b[ni]);
        }
    }
}

// ---------------------------------------------------------------------------
// Fused QKV projection: z = 0/1/2 -> Q/K (RoPE) / V (transposed write).
// ---------------------------------------------------------------------------
__global__ __launch_bounds__(256, 2)
void qkv_f16(const float* __restrict__ fc, const float* __restrict__ fs)
{
    extern __shared__ __half smh[];
    const int tid = threadIdx.x;
    const int m0 = blockIdx.y * 128, n0 = blockIdx.x * 128;
    const int z = blockIdx.z;
    const int warp = tid >> 5, lane = tid & 31;
    const int wm = warp & 3, wn = warp >> 2;
    const int g = lane >> 2, tig = lane & 3;

    float acc[2][8][4];
    #pragma unroll
    for (int mi = 0; mi < 2; mi++)
        #pragma unroll
        for (int ni = 0; ni < 8; ni++)
            #pragma unroll
            for (int j = 0; j < 4; j++) acc[mi][ni][j] = 0.f;

    run_gemm(acc, g_Xt, g_Wt + (size_t)z * DD * DD, m0, n0, smh, tid);

    #pragma unroll
    for (int mi = 0; mi < 2; mi++) {
        #pragma unroll
        for (int ni = 0; ni < 8; ni++) {
            const int m = m0 + wm * 32 + mi * 16 + g;
            const int n = n0 + wn * 64 + ni * 8 + 2 * tig;
            float c0 = acc[mi][ni][0], c1 = acc[mi][ni][1];
            float c2 = acc[mi][ni][2], c3 = acc[mi][ni][3];
            const int b = m >> 11, sl = m & (SS - 1);
            const int h = n >> 6, d = n & 63;
            const int bh = b * HH + h;
            if (z == 2) {
                size_t ov = ((size_t)bh * HDIM + d) * SS + sl;
                g_V[ov]          = __float2half_rn(c0);
                g_V[ov + SS]     = __float2half_rn(c1);
                g_V[ov + 8]      = __float2half_rn(c2);
                g_V[ov + SS + 8] = __float2half_rn(c3);
            } else {
                const int f = d >> 1;
                float cA = fc[sl * 32 + f],       sA = fs[sl * 32 + f];
                float cB = fc[(sl + 8) * 32 + f], sB = fs[(sl + 8) * 32 + f];
                float v0 = c0 * cA - c1 * sA, v1 = c0 * sA + c1 * cA;
                float v2 = c2 * cB - c3 * sB, v3 = c2 * sB + c3 * cB;
                __half* dstq = (z == 0) ? g_Q : g_K;
                size_t o = ((size_t)bh * SS + sl) * HDIM + d;
                *(uint32_t*)&dstq[o]            = h2(v0, v1);
                *(uint32_t*)&dstq[o + 8 * HDIM] = h2(v2, v3);
            }
        }
    }
}

// ---------------------------------------------------------------------------
// Output projection: g_AO @ wo -> fp32 out.
// ---------------------------------------------------------------------------
__global__ __launch_bounds__(256, 2)
void gemm_o(float* __restrict__ out)
{
    extern __shared__ __half smh[];
    const int tid = threadIdx.x;
    const int m0 = blockIdx.y * 128, n0 = blockIdx.x * 128;
    const int warp = tid >> 5, lane = tid & 31;
    const int wm = warp & 3, wn = warp >> 2;
    const int g = lane >> 2, tig = lane & 3;

    float acc[2][8][4];
    #pragma unroll
    for (int mi = 0; mi < 2; mi++)
        #pragma unroll
        for (int ni = 0; ni < 8; ni++)
            #pragma unroll
            for (int j = 0; j < 4; j++) acc[mi][ni][j] = 0.f;

    run_gemm(acc, g_AO, g_Wt + (size_t)3 * DD * DD, m0, n0, smh, tid);

    #pragma unroll
    for (int mi = 0; mi < 2; mi++) {
        #pragma unroll
        for (int ni = 0; ni < 8; ni++) {
            const int m = m0 + wm * 32 + mi * 16 + g;
            const int n = n0 + wn * 64 + ni * 8 + 2 * tig;
            *(float2*)&out[(size_t)m * DD + n] =
                make_float2(acc[mi][ni][0], acc[mi][ni][1]);
            *(float2*)&out[(size_t)(m + 8) * DD + n] =
                make_float2(acc[mi][ni][2], acc[mi][ni][3]);
        }
    }
}

// ---------------------------------------------------------------------------
// Flash attention fp16. 128 thr = 4 warps x 32 q-rows (2 m-frags each);
// 128 q rows/CTA; each K/V fragment load now feeds 2 mma (LDS/mma = 1.0).
// 64-key tiles, 3-stage cp.async, one barrier/iter; P in registers.
// Smem: stage s at s*18432 B (K 9216 + Vt 9216). Total 55296 B.
// ---------------------------------------------------------------------------
__device__ __forceinline__ void attn_load(uint32_t smb, int stage,
                                          const __half* Kg, const __half* Vtg,
                                          int kt, int tid) {
    uint32_t ks = smb + (uint32_t)stage * 18432u;
    uint32_t vs = ks + 9216u;
    #pragma unroll
    for (int i = 0; i < 4; i++) {
        int c = tid + i * 128;
        int r = c >> 3, cb = (c & 7) * 16;
        cpa16(ks + (uint32_t)(r * 144 + cb), Kg + (size_t)(kt * 64 + r) * HDIM + (c & 7) * 8);
        cpa16(vs + (uint32_t)(r * 144 + cb), Vtg + (size_t)r * SS + kt * 64 + (c & 7) * 8);
    }
    cpcommit();
}

#define SCL 0.18033688f   // 0.125 * log2(e)

__global__ __launch_bounds__(128, 2)
void attn_f16()
{
    extern __shared__ __half smh[];
    const int tid = threadIdx.x, warp = tid >> 5, lane = tid & 31;
    const int g = lane >> 2, tig = lane & 3;
    const int qb = gridDim.x - 1 - blockIdx.x;   // heaviest tiles first
    const int bh = blockIdx.y;
    const size_t base = (size_t)bh * SS * HDIM;
    const int lim = 2 * qb + 1;
    const int mylim = 2 * qb + (warp >> 1);      // warps 0,1 skip last tile
    const int rbase = qb * 128 + warp * 32;
    const uint32_t smb = (uint32_t)__cvta_generic_to_shared(smh);

    // Q fragments, 2 m-frags of 16 rows. aq[mf][kk] covers dims 16kk..+15.
    uint32_t aq[2][4][4];
    #pragma unroll
    for (int mf = 0; mf < 2; mf++) {
        const __half* Q0 = g_Q + base + (size_t)(rbase + mf * 16 + g) * HDIM;
        #pragma unroll
        for (int kk = 0; kk < 4; kk++) {
            int c = kk * 16 + 2 * tig;
            aq[mf][kk][0] = *(const uint32_t*)&Q0[c];
            aq[mf][kk][1] = *(const uint32_t*)&Q0[8 * HDIM + c];
            aq[mf][kk][2] = *(const uint32_t*)&Q0[c + 8];
            aq[mf][kk][3] = *(const uint32_t*)&Q0[8 * HDIM + c + 8];
        }
    }

    float oacc[2][8][4];
    #pragma unroll
    for (int mf = 0; mf < 2; mf++)
        #pragma unroll
        for (int ni = 0; ni < 8; ni++)
            #pragma unroll
            for (int j = 0; j < 4; j++) oacc[mf][ni][j] = 0.f;
    float mx[4] = {-1e30f, -1e30f, -1e30f, -1e30f};
    float lv[4] = {0.f, 0.f, 0.f, 0.f};

    const __half* Kg  = g_K + base;
    const __half* Vtg = g_V + base;

    attn_load(smb, 0, Kg, Vtg, 0, tid);
    attn_load(smb, 1, Kg, Vtg, 1, tid);

    for (int kt = 0; kt <= lim; kt++) {
        if (kt < lim) cpwait<1>(); else cpwait<0>();
        __syncthreads();
        if (kt + 2 <= lim)
            attn_load(smb, (kt + 2) % 3, Kg, Vtg, kt + 2, tid);

        if (kt <= mylim) {
            const __half* Ks = smh + (kt % 3) * 9216;
            const __half* Vt = Ks + 4608;

            // S = Q @ K^T  (keys = n, dims = k); each b frag feeds 2 mma
            float sc[2][8][4];
            #pragma unroll
            for (int mf = 0; mf < 2; mf++)
                #pragma unroll
                for (int ni = 0; ni < 8; ni++)
                    #pragma unroll
                    for (int j = 0; j < 4; j++) sc[mf][ni][j] = 0.f;
            #pragma unroll
            for (int kk = 0; kk < 4; kk++) {
                uint32_t b[8][2];
                #pragma unroll
                for (int ni = 0; ni < 8; ni++) {
                    int cb = (ni * 8 + g) * 72 + kk * 16 + 2 * tig;
                    b[ni][0] = *(const uint32_t*)&Ks[cb];
                    b[ni][1] = *(const uint32_t*)&Ks[cb + 8];
                }
                #pragma unroll
                for (int mf = 0; mf < 2; mf++)
                    #pragma unroll
                    for (int ni = 0; ni < 8; ni++)
                        mmaf16(sc[mf][ni], aq[mf][kk], b[ni]);
            }

            // scale (log2 domain) + causal mask on diagonal tile + row max
            const bool diag = (kt == mylim);
            float nm[4] = {mx[0], mx[1], mx[2], mx[3]};
            #pragma unroll
            for (int mf = 0; mf < 2; mf++) {
                const int rowA = rbase + mf * 16 + g;
                const int rowB = rowA + 8;
                #pragma unroll
                for (int ni = 0; ni < 8; ni++) {
                    int col = kt * 64 + ni * 8 + 2 * tig;
                    #pragma unroll
                    for (int j = 0; j < 4; j++) sc[mf][ni][j] *= SCL;
                    if (diag) {
                        if (col     > rowA) sc[mf][ni][0] = -1e30f;
                        if (col + 1 > rowA) sc[mf][ni][1] = -1e30f;
                        if (col     > rowB) sc[mf][ni][2] = -1e30f;
                        if (col + 1 > rowB) sc[mf][ni][3] = -1e30f;
                    }
                    nm[2*mf]   = fmaxf(nm[2*mf],   fmaxf(sc[mf][ni][0], sc[mf][ni][1]));
                    nm[2*mf+1] = fmaxf(nm[2*mf+1], fmaxf(sc[mf][ni][2], sc[mf][ni][3]));
                }
            }
            #pragma unroll
            for (int j = 0; j < 4; j++) {
                nm[j] = fmaxf(nm[j], __shfl_xor_sync(0xffffffffu, nm[j], 1));
                nm[j] = fmaxf(nm[j], __shfl_xor_sync(0xffffffffu, nm[j], 2));
            }
            float corr[4];
            #pragma unroll
            for (int j = 0; j < 4; j++) {
                corr[j] = ex2(mx[j] - nm[j]);
                mx[j] = nm[j];
            }

            // exp in place; accumulate row sums
            float ls[4] = {0.f, 0.f, 0.f, 0.f};
            #pragma unroll
            for (int mf = 0; mf < 2; mf++)
                #pragma unroll
                for (int ni = 0; ni < 8; ni++) {
                    sc[mf][ni][0] = ex2(sc[mf][ni][0] - mx[2*mf]);
                    sc[mf][ni][1] = ex2(sc[mf][ni][1] - mx[2*mf]);
                    sc[mf][ni][2] = ex2(sc[mf][ni][2] - mx[2*mf+1]);
                    sc[mf][ni][3] = ex2(sc[mf][ni][3] - mx[2*mf+1]);
                    ls[2*mf]   += sc[mf][ni][0] + sc[mf][ni][1];
                    ls[2*mf+1] += sc[mf][ni][2] + sc[mf][ni][3];
                }
            #pragma unroll
            for (int j = 0; j < 4; j++) lv[j] = lv[j] * corr[j] + ls[j];
            #pragma unroll
            for (int mf = 0; mf < 2; mf++)
                #pragma unroll
                for (int ni = 0; ni < 8; ni++) {
                    oacc[mf][ni][0] *= corr[2*mf];   oacc[mf][ni][1] *= corr[2*mf];
                    oacc[mf][ni][2] *= corr[2*mf+1]; oacc[mf][ni][3] *= corr[2*mf+1];
                }

            // O += P @ V  (dims = n via Vt rows, keys = k); b feeds 2 mma
            #pragma unroll
            for (int kk = 0; kk < 4; kk++) {
                uint32_t pa[2][4];
                #pragma unroll
                for (int mf = 0; mf < 2; mf++) {
                    pa[mf][0] = h2(sc[mf][2*kk][0],   sc[mf][2*kk][1]);
                    pa[mf][1] = h2(sc[mf][2*kk][2],   sc[mf][2*kk][3]);
                    pa[mf][2] = h2(sc[mf][2*kk+1][0], sc[mf][2*kk+1][1]);
                    pa[mf][3] = h2(sc[mf][2*kk+1][2], sc[mf][2*kk+1][3]);
                }
                uint32_t b[8][2];
                #pragma unroll
                for (int ni = 0; ni < 8; ni++) {
                    int cb = (ni * 8 + g) * 72 + kk * 16 + 2 * tig;
                    b[ni][0] = *(const uint32_t*)&Vt[cb];
                    b[ni][1] = *(const uint32_t*)&Vt[cb + 8];
                }
                #pragma unroll
                for (int mf = 0; mf < 2; mf++)
                    #pragma unroll
                    for (int ni = 0; ni < 8; ni++)
                        mmaf16(oacc[mf][ni], pa[mf], b[ni]);
            }
        }
    }

    // Finalize
    #pragma unroll
    for (int j = 0; j < 4; j++) {
        lv[j] += __shfl_xor_sync(0xffffffffu, lv[j], 1);
        lv[j] += __shfl_xor_sync(0xffffffffu, lv[j], 2);
        lv[j] = 1.f / lv[j];
    }
    const int b = bh >> 4, h = bh & 15;
    #pragma unroll
    for (int mf = 0; mf < 2; mf++) {
        const int rowA = rbase + mf * 16 + g;
        #pragma unroll
        for (int ni = 0; ni < 8; ni++) {
            int col = ni * 8 + 2 * tig;
            size_t o0 = ((size_t)(b * SS + rowA)) * DD + h * HDIM + col;
            size_t o1 = ((size_t)(b * SS + rowA + 8)) * DD + h * HDIM + col;
            *(uint32_t*)&g_AO[o0] = h2(oacc[mf][ni][0] * lv[2*mf],
                                       oacc[mf][ni][1] * lv[2*mf]);
            *(uint32_t*)&g_AO[o1] = h2(oacc[mf][ni][2] * lv[2*mf+1],
                                       oacc[mf][ni][3] * lv[2*mf+1]);
        }
    }
}

// ---------------------------------------------------------------------------
extern "C" void kernel_launch(void* const* d_in, const int* in_sizes, int n_in,
                              void* d_out, int out_size)
{
    const float* x  = (const float*)d_in[0];
    const float* fc = (const float*)d_in[1];
    const float* fs = (const float*)d_in[2];
    float* out = (float*)d_out;

    const int gemm_smem = 3 * 36864;   // 110592
    const int attn_smem = 3 * 18432;   // 55296
    cudaFuncSetAttribute(qkv_f16, cudaFuncAttributeMaxDynamicSharedMemorySize, gemm_smem);
    cudaFuncSetAttribute(gemm_o,  cudaFuncAttributeMaxDynamicSharedMemorySize, gemm_smem);
    cudaFuncSetAttribute(attn_f16, cudaFuncAttributeMaxDynamicSharedMemorySize, attn_smem);

    const int ncvt = N4X + 4 * N4W;    // 3145728
    cvt_all<<<ncvt / 512, 256>>>((const float4*)x,
                                 (const float4*)d_in[3], (const float4*)d_in[4],
                                 (const float4*)d_in[5], (const float4*)d_in[6]);

    dim3 gq(DD / 128, MM / 128, 3);    // (8, 64, 3)
    qkv_f16<<<gq, 256, gemm_smem>>>(fc, fs);

    dim3 ag(SS / 128, BB * HH);        // (16, 64)
    attn_f16<<<ag, 128, attn_smem>>>();

    dim3 go(DD / 128, MM / 128);       // (8, 64)
    gemm_o<<<go, 256, gemm_smem>>>(out);
}

// round 15
// speedup vs baseline: 1.4814x; 1.0122x over previous
#include <cuda_runtime.h>
#include <cuda_fp16.h>
#include <stdint.h>

#define BB 4
#define SS 2048
#define DD 1024
#define HH 16
#define HDIM 64
#define MM (BB*SS)   // 8192

// Scratch (allocation-free rule: __device__ globals). All fp16.
__device__ __half g_Xt[(size_t)MM*DD];
__device__ __half g_Wt[(size_t)4*DD*DD];    // wq,wk,wv,wo
__device__ __half g_Q [(size_t)MM*DD];      // [B,H,S,HD]
__device__ __half g_K [(size_t)MM*DD];
__device__ __half g_V [(size_t)MM*DD];      // TRANSPOSED: [B,H,HD,S]
__device__ __half g_AO[(size_t)MM*DD];      // [B,S,D]

__device__ __forceinline__ float ex2(float x) {
    float r;
    asm("ex2.approx.f32 %0, %1;" : "=f"(r) : "f"(x));
    return r;
}
__device__ __forceinline__ uint32_t h2(float a, float b) {
    __half2 h = __floats2half2_rn(a, b);
    return *(uint32_t*)&h;
}
__device__ __forceinline__ void mmaf16(float* c, const uint32_t* a, const uint32_t* b) {
    asm volatile(
        "mma.sync.aligned.m16n8k16.row.col.f32.f16.f16.f32 "
        "{%0,%1,%2,%3},{%4,%5,%6,%7},{%8,%9},{%0,%1,%2,%3};"
        : "+f"(c[0]), "+f"(c[1]), "+f"(c[2]), "+f"(c[3])
        : "r"(a[0]), "r"(a[1]), "r"(a[2]), "r"(a[3]), "r"(b[0]), "r"(b[1]));
}
__device__ __forceinline__ void cpa16(uint32_t dst, const void* src) {
    asm volatile("cp.async.cg.shared.global [%0], [%1], 16;" :: "r"(dst), "l"(src));
}
__device__ __forceinline__ void cpcommit() {
    asm volatile("cp.async.commit_group;");
}
template<int N> __device__ __forceinline__ void cpwait() {
    asm volatile("cp.async.wait_group %0;" :: "n"(N));
}

// ---------------------------------------------------------------------------
// Fused prepass: fp32 -> fp16 (RN), ILP=2.
// ---------------------------------------------------------------------------
#define N4X (MM*DD/4)       // 2097152
#define N4W (DD*DD/4)       // 262144 = 2^18
__device__ __forceinline__ void cvt_one(int i,
        const float4* x, const float4* wq, const float4* wk,
        const float4* wv, const float4* wo) {
    const float4* src;
    __half* dst;
    int j;
    if (i < N4X) {
        src = x; dst = g_Xt; j = i;
    } else {
        int k = i - N4X;
        int w = k >> 18;
        j = k & (N4W - 1);
        src = (w == 0) ? wq : (w == 1) ? wk : (w == 2) ? wv : wo;
        dst = g_Wt + (size_t)w * DD * DD;
    }
    float4 v = src[j];
    *(uint2*)&dst[(size_t)j * 4] = make_uint2(h2(v.x, v.y), h2(v.z, v.w));
}
__global__ void cvt_all(const float4* __restrict__ x,
                        const float4* __restrict__ wq, const float4* __restrict__ wk,
                        const float4* __restrict__ wv, const float4* __restrict__ wo) {
    int i = blockIdx.x * 512 + threadIdx.x;
    cvt_one(i, x, wq, wk, wv, wo);
    cvt_one(i + 256, x, wq, wk, wv, wo);
}

// ---------------------------------------------------------------------------
// Shared GEMM mainloop: acc = A[M,K] @ B[N,K]^T for one 128x128 CTA tile.
// 128 threads = 4 warps x 64x64 warp tiles (LDS/mma = 1.0, smem-traffic
// relief so the tensor pipe binds). K-slab 64, 3-stage cp.async, one
// barrier per iteration. Scalar-LDS fragments.
// ---------------------------------------------------------------------------
__device__ __forceinline__ void g_load(uint32_t smb, int s,
                                       const __half* Ag, const __half* Bg,
                                       int m0, int n0, int k0, int tid) {
    uint32_t sa = smb + (uint32_t)s * 36864u;
    uint32_t sb = sa + 18432u;
    #pragma unroll
    for (int i = 0; i < 8; i++) {
        int c = tid + i * 128;
        int r = c >> 3, cb = (c & 7) * 16;
        cpa16(sa + (uint32_t)(r * 144 + cb), Ag + (size_t)(m0 + r) * DD + k0 + (c & 7) * 8);
    }
    #pragma unroll
    for (int i = 0; i < 8; i++) {
        int c = tid + i * 128;
        int r = c >> 3, cb = (c & 7) * 16;
        cpa16(sb + (uint32_t)(r * 144 + cb), Bg + (size_t)(n0 + r) * DD + k0 + (c & 7) * 8);
    }
    cpcommit();
}

__device__ __forceinline__ void run_gemm(float acc[4][8][4],
                                         const __half* Ag, const __half* Bg,
                                         int m0, int n0, __half* smh, int tid)
{
    const int warp = tid >> 5, lane = tid & 31;
    const int wm = warp & 1, wn = warp >> 1;
    const int g = lane >> 2, tig = lane & 3;
    const uint32_t smb = (uint32_t)__cvta_generic_to_shared(smh);

    g_load(smb, 0, Ag, Bg, m0, n0, 0,  tid);
    g_load(smb, 1, Ag, Bg, m0, n0, 64, tid);

    for (int t = 0; t < 16; t++) {
        if (t < 15) cpwait<1>(); else cpwait<0>();
        __syncthreads();
        if (t + 2 < 16)
            g_load(smb, (t + 2) % 3, Ag, Bg, m0, n0, (t + 2) * 64, tid);

        const __half* As = smh + (t % 3) * 18432;
        const __half* Bs = As + 9216;
        #pragma unroll
        for (int ks = 0; ks < 4; ks++) {
            uint32_t a[4][4], b[8][2];
            #pragma unroll
            for (int mi = 0; mi < 4; mi++) {
                int cb = (wm * 64 + mi * 16 + g) * 72 + ks * 16 + 2 * tig;
                a[mi][0] = *(const uint32_t*)&As[cb];
                a[mi][1] = *(const uint32_t*)&As[cb + 8 * 72];
                a[mi][2] = *(const uint32_t*)&As[cb + 8];
                a[mi][3] = *(const uint32_t*)&As[cb + 8 * 72 + 8];
            }
            #pragma unroll
            for (int ni = 0; ni < 8; ni++) {
                int cb = (wn * 64 + ni * 8 + g) * 72 + ks * 16 + 2 * tig;
                b[ni][0] = *(const uint32_t*)&Bs[cb];
                b[ni][1] = *(const uint32_t*)&Bs[cb + 8];
            }
            #pragma unroll
            for (int mi = 0; mi < 4; mi++)
                #pragma unroll
                for (int ni = 0; ni < 8; ni++)
                    mmaf16(acc[mi][ni], a[mi], b[ni]);
        }
    }
}

// ---------------------------------------------------------------------------
// Fused QKV projection: z = 0/1/2 -> Q/K (RoPE) / V (transposed write).
// ---------------------------------------------------------------------------
__global__ __launch_bounds__(128, 2)
void qkv_f16(const float* __restrict__ fc, const float* __restrict__ fs)
{
    extern __shared__ __half smh[];
    const int tid = threadIdx.x;
    const int m0 = blockIdx.y * 128, n0 = blockIdx.x * 128;
    const int z = blockIdx.z;
    const int warp = tid >> 5, lane = tid & 31;
    const int wm = warp & 1, wn = warp >> 1;
    const int g = lane >> 2, tig = lane & 3;

    float acc[4][8][4];
    #pragma unroll
    for (int mi = 0; mi < 4; mi++)
        #pragma unroll
        for (int ni = 0; ni < 8; ni++)
            #pragma unroll
            for (int j = 0; j < 4; j++) acc[mi][ni][j] = 0.f;

    run_gemm(acc, g_Xt, g_Wt + (size_t)z * DD * DD, m0, n0, smh, tid);

    #pragma unroll
    for (int mi = 0; mi < 4; mi++) {
        #pragma unroll
        for (int ni = 0; ni < 8; ni++) {
            const int m = m0 + wm * 64 + mi * 16 + g;
            const int n = n0 + wn * 64 + ni * 8 + 2 * tig;
            float c0 = acc[mi][ni][0], c1 = acc[mi][ni][1];
            float c2 = acc[mi][ni][2], c3 = acc[mi][ni][3];
            const int b = m >> 11, sl = m & (SS - 1);
            const int h = n >> 6, d = n & 63;
            const int bh = b * HH + h;
            if (z == 2) {
                size_t ov = ((size_t)bh * HDIM + d) * SS + sl;
                g_V[ov]          = __float2half_rn(c0);
                g_V[ov + SS]     = __float2half_rn(c1);
                g_V[ov + 8]      = __float2half_rn(c2);
                g_V[ov + SS + 8] = __float2half_rn(c3);
            } else {
                const int f = d >> 1;
                float cA = fc[sl * 32 + f],       sA = fs[sl * 32 + f];
                float cB = fc[(sl + 8) * 32 + f], sB = fs[(sl + 8) * 32 + f];
                float v0 = c0 * cA - c1 * sA, v1 = c0 * sA + c1 * cA;
                float v2 = c2 * cB - c3 * sB, v3 = c2 * sB + c3 * cB;
                __half* dstq = (z == 0) ? g_Q : g_K;
                size_t o = ((size_t)bh * SS + sl) * HDIM + d;
                *(uint32_t*)&dstq[o]            = h2(v0, v1);
                *(uint32_t*)&dstq[o + 8 * HDIM] = h2(v2, v3);
            }
        }
    }
}

// ---------------------------------------------------------------------------
// Output projection: g_AO @ wo -> fp32 out.
// ---------------------------------------------------------------------------
__global__ __launch_bounds__(128, 2)
void gemm_o(float* __restrict__ out)
{
    extern __shared__ __half smh[];
    const int tid = threadIdx.x;
    const int m0 = blockIdx.y * 128, n0 = blockIdx.x * 128;
    const int warp = tid >> 5, lane = tid & 31;
    const int wm = warp & 1, wn = warp >> 1;
    const int g = lane >> 2, tig = lane & 3;

    float acc[4][8][4];
    #pragma unroll
    for (int mi = 0; mi < 4; mi++)
        #pragma unroll
        for (int ni = 0; ni < 8; ni++)
            #pragma unroll
            for (int j = 0; j < 4; j++) acc[mi][ni][j] = 0.f;

    run_gemm(acc, g_AO, g_Wt + (size_t)3 * DD * DD, m0, n0, smh, tid);

    #pragma unroll
    for (int mi = 0; mi < 4; mi++) {
        #pragma unroll
        for (int ni = 0; ni < 8; ni++) {
            const int m = m0 + wm * 64 + mi * 16 + g;
            const int n = n0 + wn * 64 + ni * 8 + 2 * tig;
            *(float2*)&out[(size_t)m * DD + n] =
                make_float2(acc[mi][ni][0], acc[mi][ni][1]);
            *(float2*)&out[(size_t)(m + 8) * DD + n] =
                make_float2(acc[mi][ni][2], acc[mi][ni][3]);
        }
    }
}

// ---------------------------------------------------------------------------
// Flash attention fp16 (unchanged from R14). 128 thr = 4 warps x 32 q-rows;
// 128 q rows/CTA; 64-key tiles, 3-stage cp.async, one barrier/iter.
// Smem: stage s at s*18432 B (K 9216 + Vt 9216). Total 55296 B.
// ---------------------------------------------------------------------------
__device__ __forceinline__ void attn_load(uint32_t smb, int stage,
                                          const __half* Kg, const __half* Vtg,
                                          int kt, int tid) {
    uint32_t ks = smb + (uint32_t)stage * 18432u;
    uint32_t vs = ks + 9216u;
    #pragma unroll
    for (int i = 0; i < 4; i++) {
        int c = tid + i * 128;
        int r = c >> 3, cb = (c & 7) * 16;
        cpa16(ks + (uint32_t)(r * 144 + cb), Kg + (size_t)(kt * 64 + r) * HDIM + (c & 7) * 8);
        cpa16(vs + (uint32_t)(r * 144 + cb), Vtg + (size_t)r * SS + kt * 64 + (c & 7) * 8);
    }
    cpcommit();
}

#define SCL 0.18033688f   // 0.125 * log2(e)

__global__ __launch_bounds__(128, 2)
void attn_f16()
{
    extern __shared__ __half smh[];
    const int tid = threadIdx.x, warp = tid >> 5, lane = tid & 31;
    const int g = lane >> 2, tig = lane & 3;
    const int qb = gridDim.x - 1 - blockIdx.x;   // heaviest tiles first
    const int bh = blockIdx.y;
    const size_t base = (size_t)bh * SS * HDIM;
    const int lim = 2 * qb + 1;
    const int mylim = 2 * qb + (warp >> 1);      // warps 0,1 skip last tile
    const int rbase = qb * 128 + warp * 32;
    const uint32_t smb = (uint32_t)__cvta_generic_to_shared(smh);

    // Q fragments, 2 m-frags of 16 rows. aq[mf][kk] covers dims 16kk..+15.
    uint32_t aq[2][4][4];
    #pragma unroll
    for (int mf = 0; mf < 2; mf++) {
        const __half* Q0 = g_Q + base + (size_t)(rbase + mf * 16 + g) * HDIM;
        #pragma unroll
        for (int kk = 0; kk < 4; kk++) {
            int c = kk * 16 + 2 * tig;
            aq[mf][kk][0] = *(const uint32_t*)&Q0[c];
            aq[mf][kk][1] = *(const uint32_t*)&Q0[8 * HDIM + c];
            aq[mf][kk][2] = *(const uint32_t*)&Q0[c + 8];
            aq[mf][kk][3] = *(const uint32_t*)&Q0[8 * HDIM + c + 8];
        }
    }

    float oacc[2][8][4];
    #pragma unroll
    for (int mf = 0; mf < 2; mf++)
        #pragma unroll
        for (int ni = 0; ni < 8; ni++)
            #pragma unroll
            for (int j = 0; j < 4; j++) oacc[mf][ni][j] = 0.f;
    float mx[4] = {-1e30f, -1e30f, -1e30f, -1e30f};
    float lv[4] = {0.f, 0.f, 0.f, 0.f};

    const __half* Kg  = g_K + base;
    const __half* Vtg = g_V + base;

    attn_load(smb, 0, Kg, Vtg, 0, tid);
    attn_load(smb, 1, Kg, Vtg, 1, tid);

    for (int kt = 0; kt <= lim; kt++) {
        if (kt < lim) cpwait<1>(); else cpwait<0>();
        __syncthreads();
        if (kt + 2 <= lim)
            attn_load(smb, (kt + 2) % 3, Kg, Vtg, kt + 2, tid);

        if (kt <= mylim) {
            const __half* Ks = smh + (kt % 3) * 9216;
            const __half* Vt = Ks + 4608;

            // S = Q @ K^T  (keys = n, dims = k); each b frag feeds 2 mma
            float sc[2][8][4];
            #pragma unroll
            for (int mf = 0; mf < 2; mf++)
                #pragma unroll
                for (int ni = 0; ni < 8; ni++)
                    #pragma unroll
                    for (int j = 0; j < 4; j++) sc[mf][ni][j] = 0.f;
            #pragma unroll
            for (int kk = 0; kk < 4; kk++) {
                uint32_t b[8][2];
                #pragma unroll
                for (int ni = 0; ni < 8; ni++) {
                    int cb = (ni * 8 + g) * 72 + kk * 16 + 2 * tig;
                    b[ni][0] = *(const uint32_t*)&Ks[cb];
                    b[ni][1] = *(const uint32_t*)&Ks[cb + 8];
                }
                #pragma unroll
                for (int mf = 0; mf < 2; mf++)
                    #pragma unroll
                    for (int ni = 0; ni < 8; ni++)
                        mmaf16(sc[mf][ni], aq[mf][kk], b[ni]);
            }

            // scale (log2 domain) + causal mask on diagonal tile + row max
            const bool diag = (kt == mylim);
            float nm[4] = {mx[0], mx[1], mx[2], mx[3]};
            #pragma unroll
            for (int mf = 0; mf < 2; mf++) {
                const int rowA = rbase + mf * 16 + g;
                const int rowB = rowA + 8;
                #pragma unroll
                for (int ni = 0; ni < 8; ni++) {
                    int col = kt * 64 + ni * 8 + 2 * tig;
                    #pragma unroll
                    for (int j = 0; j < 4; j++) sc[mf][ni][j] *= SCL;
                    if (diag) {
                        if (col     > rowA) sc[mf][ni][0] = -1e30f;
                        if (col + 1 > rowA) sc[mf][ni][1] = -1e30f;
                        if (col     > rowB) sc[mf][ni][2] = -1e30f;
                        if (col + 1 > rowB) sc[mf][ni][3] = -1e30f;
                    }
                    nm[2*mf]   = fmaxf(nm[2*mf],   fmaxf(sc[mf][ni][0], sc[mf][ni][1]));
                    nm[2*mf+1] = fmaxf(nm[2*mf+1], fmaxf(sc[mf][ni][2], sc[mf][ni][3]));
                }
            }
            #pragma unroll
            for (int j = 0; j < 4; j++) {
                nm[j] = fmaxf(nm[j], __shfl_xor_sync(0xffffffffu, nm[j], 1));
                nm[j] = fmaxf(nm[j], __shfl_xor_sync(0xffffffffu, nm[j], 2));
            }
            float corr[4];
            #pragma unroll
            for (int j = 0; j < 4; j++) {
                corr[j] = ex2(mx[j] - nm[j]);
                mx[j] = nm[j];
            }

            // exp in place; accumulate row sums
            float ls[4] = {0.f, 0.f, 0.f, 0.f};
            #pragma unroll
            for (int mf = 0; mf < 2; mf++)
                #pragma unroll
                for (int ni = 0; ni < 8; ni++) {
                    sc[mf][ni][0] = ex2(sc[mf][ni][0] - mx[2*mf]);
                    sc[mf][ni][1] = ex2(sc[mf][ni][1] - mx[2*mf]);
                    sc[mf][ni][2] = ex2(sc[mf][ni][2] - mx[2*mf+1]);
                    sc[mf][ni][3] = ex2(sc[mf][ni][3] - mx[2*mf+1]);
                    ls[2*mf]   += sc[mf][ni][0] + sc[mf][ni][1];
                    ls[2*mf+1] += sc[mf][ni][2] + sc[mf][ni][3];
                }
            #pragma unroll
            for (int j = 0; j < 4; j++) lv[j] = lv[j] * corr[j] + ls[j];
            #pragma unroll
            for (int mf = 0; mf < 2; mf++)
                #pragma unroll
                for (int ni = 0; ni < 8; ni++) {
                    oacc[mf][ni][0] *= corr[2*mf];   oacc[mf][ni][1] *= corr[2*mf];
                    oacc[mf][ni][2] *= corr[2*mf+1]; oacc[mf][ni][3] *= corr[2*mf+1];
                }

            // O += P @ V  (dims = n via Vt rows, keys = k); b feeds 2 mma
            #pragma unroll
            for (int kk = 0; kk < 4; kk++) {
                uint32_t pa[2][4];
                #pragma unroll
                for (int mf = 0; mf < 2; mf++) {
                    pa[mf][0] = h2(sc[mf][2*kk][0],   sc[mf][2*kk][1]);
                    pa[mf][1] = h2(sc[mf][2*kk][2],   sc[mf][2*kk][3]);
                    pa[mf][2] = h2(sc[mf][2*kk+1][0], sc[mf][2*kk+1][1]);
                    pa[mf][3] = h2(sc[mf][2*kk+1][2], sc[mf][2*kk+1][3]);
                }
                uint32_t b[8][2];
                #pragma unroll
                for (int ni = 0; ni < 8; ni++) {
                    int cb = (ni * 8 + g) * 72 + kk * 16 + 2 * tig;
                    b[ni][0] = *(const uint32_t*)&Vt[cb];
                    b[ni][1] = *(const uint32_t*)&Vt[cb + 8];
                }
                #pragma unroll
                for (int mf = 0; mf < 2; mf++)
                    #pragma unroll
                    for (int ni = 0; ni < 8; ni++)
                        mmaf16(oacc[mf][ni], pa[mf], b[ni]);
            }
        }
    }

    // Finalize
    #pragma unroll
    for (int j = 0; j < 4; j++) {
        lv[j] += __shfl_xor_sync(0xffffffffu, lv[j], 1);
        lv[j] += __shfl_xor_sync(0xffffffffu, lv[j], 2);
        lv[j] = 1.f / lv[j];
    }
    const int b = bh >> 4, h = bh & 15;
    #pragma unroll
    for (int mf = 0; mf < 2; mf++) {
        const int rowA = rbase + mf * 16 + g;
        #pragma unroll
        for (int ni = 0; ni < 8; ni++) {
            int col = ni * 8 + 2 * tig;
            size_t o0 = ((size_t)(b * SS + rowA)) * DD + h * HDIM + col;
            size_t o1 = ((size_t)(b * SS + rowA + 8)) * DD + h * HDIM + col;
            *(uint32_t*)&g_AO[o0] = h2(oacc[mf][ni][0] * lv[2*mf],
                                       oacc[mf][ni][1] * lv[2*mf]);
            *(uint32_t*)&g_AO[o1] = h2(oacc[mf][ni][2] * lv[2*mf+1],
                                       oacc[mf][ni][3] * lv[2*mf+1]);
        }
    }
}

// ---------------------------------------------------------------------------
extern "C" void kernel_launch(void* const* d_in, const int* in_sizes, int n_in,
                              void* d_out, int out_size)
{
    const float* x  = (const float*)d_in[0];
    const float* fc = (const float*)d_in[1];
    const float* fs = (const float*)d_in[2];
    float* out = (float*)d_out;

    const int gemm_smem = 3 * 36864;   // 110592
    const int attn_smem = 3 * 18432;   // 55296
    cudaFuncSetAttribute(qkv_f16, cudaFuncAttributeMaxDynamicSharedMemorySize, gemm_smem);
    cudaFuncSetAttribute(gemm_o,  cudaFuncAttributeMaxDynamicSharedMemorySize, gemm_smem);
    cudaFuncSetAttribute(attn_f16, cudaFuncAttributeMaxDynamicSharedMemorySize, attn_smem);

    const int ncvt = N4X + 4 * N4W;    // 3145728
    cvt_all<<<ncvt / 512, 256>>>((const float4*)x,
                                 (const float4*)d_in[3], (const float4*)d_in[4],
                                 (const float4*)d_in[5], (const float4*)d_in[6]);

    dim3 gq(DD / 128, MM / 128, 3);    // (8, 64, 3)
    qkv_f16<<<gq, 128, gemm_smem>>>(fc, fs);

    dim3 ag(SS / 128, BB * HH);        // (16, 64)
    attn_f16<<<ag, 128, attn_smem>>>();

    dim3 go(DD / 128, MM / 128);       // (8, 64)
    gemm_o<<<go, 128, gemm_smem>>>(out);
}

// round 16
// speedup vs baseline: 1.6476x; 1.1122x over previous
#include <cuda_runtime.h>
#include <cuda_fp16.h>
#include <stdint.h>

#define BB 4
#define SS 2048
#define DD 1024
#define HH 16
#define HDIM 64
#define MM (BB*SS)   // 8192

// Scratch (allocation-free rule: __device__ globals). All fp16.
__device__ __half g_Xt[(size_t)MM*DD];
__device__ __half g_Wt[(size_t)4*DD*DD];    // wq,wk,wv,wo
__device__ __half g_Q [(size_t)MM*DD];      // [B,H,S,HD]
__device__ __half g_K [(size_t)MM*DD];
__device__ __half g_V [(size_t)MM*DD];      // TRANSPOSED: [B,H,HD,S]
__device__ __half g_AO[(size_t)MM*DD];      // [B,S,D]

__device__ __forceinline__ float ex2(float x) {
    float r;
    asm("ex2.approx.f32 %0, %1;" : "=f"(r) : "f"(x));
    return r;
}
__device__ __forceinline__ uint32_t h2(float a, float b) {
    __half2 h = __floats2half2_rn(a, b);
    return *(uint32_t*)&h;
}
__device__ __forceinline__ void mmaf16(float* c, const uint32_t* a, const uint32_t* b) {
    asm volatile(
        "mma.sync.aligned.m16n8k16.row.col.f32.f16.f16.f32 "
        "{%0,%1,%2,%3},{%4,%5,%6,%7},{%8,%9},{%0,%1,%2,%3};"
        : "+f"(c[0]), "+f"(c[1]), "+f"(c[2]), "+f"(c[3])
        : "r"(a[0]), "r"(a[1]), "r"(a[2]), "r"(a[3]), "r"(b[0]), "r"(b[1]));
}
__device__ __forceinline__ void cpa16(uint32_t dst, const void* src) {
    asm volatile("cp.async.cg.shared.global [%0], [%1], 16;" :: "r"(dst), "l"(src));
}
__device__ __forceinline__ void cpcommit() {
    asm volatile("cp.async.commit_group;");
}
template<int N> __device__ __forceinline__ void cpwait() {
    asm volatile("cp.async.wait_group %0;" :: "n"(N));
}

// ---------------------------------------------------------------------------
// Fused prepass: fp32 -> fp16 (RN), ILP=4.
// ---------------------------------------------------------------------------
#define N4X (MM*DD/4)       // 2097152
#define N4W (DD*DD/4)       // 262144 = 2^18
__device__ __forceinline__ void cvt_one(int i,
        const float4* x, const float4* wq, const float4* wk,
        const float4* wv, const float4* wo) {
    const float4* src;
    __half* dst;
    int j;
    if (i < N4X) {
        src = x; dst = g_Xt; j = i;
    } else {
        int k = i - N4X;
        int w = k >> 18;
        j = k & (N4W - 1);
        src = (w == 0) ? wq : (w == 1) ? wk : (w == 2) ? wv : wo;
        dst = g_Wt + (size_t)w * DD * DD;
    }
    float4 v = src[j];
    *(uint2*)&dst[(size_t)j * 4] = make_uint2(h2(v.x, v.y), h2(v.z, v.w));
}
__global__ void cvt_all(const float4* __restrict__ x,
                        const float4* __restrict__ wq, const float4* __restrict__ wk,
                        const float4* __restrict__ wv, const float4* __restrict__ wo) {
    int i = blockIdx.x * 1024 + threadIdx.x;
    cvt_one(i,       x, wq, wk, wv, wo);
    cvt_one(i + 256, x, wq, wk, wv, wo);
    cvt_one(i + 512, x, wq, wk, wv, wo);
    cvt_one(i + 768, x, wq, wk, wv, wo);
}

// ---------------------------------------------------------------------------
// Shared GEMM mainloop: acc = A[M,K] @ B[N,K]^T for one 128x128 CTA tile.
// 128 threads = 4 warps x 64x64 warp tiles. K-slab 64, 3-stage cp.async,
// one barrier per iteration. Scalar-LDS fragments.
// ---------------------------------------------------------------------------
__device__ __forceinline__ void g_load(uint32_t smb, int s,
                                       const __half* Ag, const __half* Bg,
                                       int m0, int n0, int k0, int tid) {
    uint32_t sa = smb + (uint32_t)s * 36864u;
    uint32_t sb = sa + 18432u;
    #pragma unroll
    for (int i = 0; i < 8; i++) {
        int c = tid + i * 128;
        int r = c >> 3, cb = (c & 7) * 16;
        cpa16(sa + (uint32_t)(r * 144 + cb), Ag + (size_t)(m0 + r) * DD + k0 + (c & 7) * 8);
    }
    #pragma unroll
    for (int i = 0; i < 8; i++) {
        int c = tid + i * 128;
        int r = c >> 3, cb = (c & 7) * 16;
        cpa16(sb + (uint32_t)(r * 144 + cb), Bg + (size_t)(n0 + r) * DD + k0 + (c & 7) * 8);
    }
    cpcommit();
}

__device__ __forceinline__ void run_gemm(float acc[4][8][4],
                                         const __half* Ag, const __half* Bg,
                                         int m0, int n0, __half* smh, int tid)
{
    const int warp = tid >> 5, lane = tid & 31;
    const int wm = warp & 1, wn = warp >> 1;
    const int g = lane >> 2, tig = lane & 3;
    const uint32_t smb = (uint32_t)__cvta_generic_to_shared(smh);

    g_load(smb, 0, Ag, Bg, m0, n0, 0,  tid);
    g_load(smb, 1, Ag, Bg, m0, n0, 64, tid);

    for (int t = 0; t < 16; t++) {
        if (t < 15) cpwait<1>(); else cpwait<0>();
        __syncthreads();
        if (t + 2 < 16)
            g_load(smb, (t + 2) % 3, Ag, Bg, m0, n0, (t + 2) * 64, tid);

        const __half* As = smh + (t % 3) * 18432;
        const __half* Bs = As + 9216;
        #pragma unroll
        for (int ks = 0; ks < 4; ks++) {
            uint32_t a[4][4], b[8][2];
            #pragma unroll
            for (int mi = 0; mi < 4; mi++) {
                int cb = (wm * 64 + mi * 16 + g) * 72 + ks * 16 + 2 * tig;
                a[mi][0] = *(const uint32_t*)&As[cb];
                a[mi][1] = *(const uint32_t*)&As[cb + 8 * 72];
                a[mi][2] = *(const uint32_t*)&As[cb + 8];
                a[mi][3] = *(const uint32_t*)&As[cb + 8 * 72 + 8];
            }
            #pragma unroll
            for (int ni = 0; ni < 8; ni++) {
                int cb = (wn * 64 + ni * 8 + g) * 72 + ks * 16 + 2 * tig;
                b[ni][0] = *(const uint32_t*)&Bs[cb];
                b[ni][1] = *(const uint32_t*)&Bs[cb + 8];
            }
            #pragma unroll
            for (int mi = 0; mi < 4; mi++)
                #pragma unroll
                for (int ni = 0; ni < 8; ni++)
                    mmaf16(acc[mi][ni], a[mi], b[ni]);
        }
    }
}

// ---------------------------------------------------------------------------
// Fused QKV projection: z = 0/1/2 -> Q/K (RoPE) / V (transposed write).
// my0: m-tile offset (batch split for stream overlap).
// ---------------------------------------------------------------------------
__global__ __launch_bounds__(128, 2)
void qkv_f16(const float* __restrict__ fc, const float* __restrict__ fs, int my0)
{
    extern __shared__ __half smh[];
    const int tid = threadIdx.x;
    const int m0 = (blockIdx.y + my0) * 128, n0 = blockIdx.x * 128;
    const int z = blockIdx.z;
    const int warp = tid >> 5, lane = tid & 31;
    const int wm = warp & 1, wn = warp >> 1;
    const int g = lane >> 2, tig = lane & 3;

    float acc[4][8][4];
    #pragma unroll
    for (int mi = 0; mi < 4; mi++)
        #pragma unroll
        for (int ni = 0; ni < 8; ni++)
            #pragma unroll
            for (int j = 0; j < 4; j++) acc[mi][ni][j] = 0.f;

    run_gemm(acc, g_Xt, g_Wt + (size_t)z * DD * DD, m0, n0, smh, tid);

    #pragma unroll
    for (int mi = 0; mi < 4; mi++) {
        #pragma unroll
        for (int ni = 0; ni < 8; ni++) {
            const int m = m0 + wm * 64 + mi * 16 + g;
            const int n = n0 + wn * 64 + ni * 8 + 2 * tig;
            float c0 = acc[mi][ni][0], c1 = acc[mi][ni][1];
            float c2 = acc[mi][ni][2], c3 = acc[mi][ni][3];
            const int b = m >> 11, sl = m & (SS - 1);
            const int h = n >> 6, d = n & 63;
            const int bh = b * HH + h;
            if (z == 2) {
                size_t ov = ((size_t)bh * HDIM + d) * SS + sl;
                g_V[ov]          = __float2half_rn(c0);
                g_V[ov + SS]     = __float2half_rn(c1);
                g_V[ov + 8]      = __float2half_rn(c2);
                g_V[ov + SS + 8] = __float2half_rn(c3);
            } else {
                const int f = d >> 1;
                float cA = fc[sl * 32 + f],       sA = fs[sl * 32 + f];
                float cB = fc[(sl + 8) * 32 + f], sB = fs[(sl + 8) * 32 + f];
                float v0 = c0 * cA - c1 * sA, v1 = c0 * sA + c1 * cA;
                float v2 = c2 * cB - c3 * sB, v3 = c2 * sB + c3 * cB;
                __half* dstq = (z == 0) ? g_Q : g_K;
                size_t o = ((size_t)bh * SS + sl) * HDIM + d;
                *(uint32_t*)&dstq[o]            = h2(v0, v1);
                *(uint32_t*)&dstq[o + 8 * HDIM] = h2(v2, v3);
            }
        }
    }
}

// ---------------------------------------------------------------------------
// Output projection: g_AO @ wo -> fp32 out. my0: m-tile offset (batch split).
// ---------------------------------------------------------------------------
__global__ __launch_bounds__(128, 2)
void gemm_o(float* __restrict__ out, int my0)
{
    extern __shared__ __half smh[];
    const int tid = threadIdx.x;
    const int m0 = (blockIdx.y + my0) * 128, n0 = blockIdx.x * 128;
    const int warp = tid >> 5, lane = tid & 31;
    const int wm = warp & 1, wn = warp >> 1;
    const int g = lane >> 2, tig = lane & 3;

    float acc[4][8][4];
    #pragma unroll
    for (int mi = 0; mi < 4; mi++)
        #pragma unroll
        for (int ni = 0; ni < 8; ni++)
            #pragma unroll
            for (int j = 0; j < 4; j++) acc[mi][ni][j] = 0.f;

    run_gemm(acc, g_AO, g_Wt + (size_t)3 * DD * DD, m0, n0, smh, tid);

    #pragma unroll
    for (int mi = 0; mi < 4; mi++) {
        #pragma unroll
        for (int ni = 0; ni < 8; ni++) {
            const int m = m0 + wm * 64 + mi * 16 + g;
            const int n = n0 + wn * 64 + ni * 8 + 2 * tig;
            *(float2*)&out[(size_t)m * DD + n] =
                make_float2(acc[mi][ni][0], acc[mi][ni][1]);
            *(float2*)&out[(size_t)(m + 8) * DD + n] =
                make_float2(acc[mi][ni][2], acc[mi][ni][3]);
        }
    }
}

// ---------------------------------------------------------------------------
// Flash attention fp16. 128 thr = 4 warps x 32 q-rows; 128 q rows/CTA;
// 64-key tiles, 3-stage cp.async, one barrier/iter. bh0: head-batch offset.
// Smem: stage s at s*18432 B (K 9216 + Vt 9216). Total 55296 B.
// ---------------------------------------------------------------------------
__device__ __forceinline__ void attn_load(uint32_t smb, int stage,
                                          const __half* Kg, const __half* Vtg,
                                          int kt, int tid) {
    uint32_t ks = smb + (uint32_t)stage * 18432u;
    uint32_t vs = ks + 9216u;
    #pragma unroll
    for (int i = 0; i < 4; i++) {
        int c = tid + i * 128;
        int r = c >> 3, cb = (c & 7) * 16;
        cpa16(ks + (uint32_t)(r * 144 + cb), Kg + (size_t)(kt * 64 + r) * HDIM + (c & 7) * 8);
        cpa16(vs + (uint32_t)(r * 144 + cb), Vtg + (size_t)r * SS + kt * 64 + (c & 7) * 8);
    }
    cpcommit();
}

#define SCL 0.18033688f   // 0.125 * log2(e)

__global__ __launch_bounds__(128, 2)
void attn_f16(int bh0)
{
    extern __shared__ __half smh[];
    const int tid = threadIdx.x, warp = tid >> 5, lane = tid & 31;
    const int g = lane >> 2, tig = lane & 3;
    const int qb = gridDim.x - 1 - blockIdx.x;   // heaviest tiles first
    const int bh = blockIdx.y + bh0;
    const size_t base = (size_t)bh * SS * HDIM;
    const int lim = 2 * qb + 1;
    const int mylim = 2 * qb + (warp >> 1);      // warps 0,1 skip last tile
    const int rbase = qb * 128 + warp * 32;
    const uint32_t smb = (uint32_t)__cvta_generic_to_shared(smh);

    // Q fragments, 2 m-frags of 16 rows. aq[mf][kk] covers dims 16kk..+15.
    uint32_t aq[2][4][4];
    #pragma unroll
    for (int mf = 0; mf < 2; mf++) {
        const __half* Q0 = g_Q + base + (size_t)(rbase + mf * 16 + g) * HDIM;
        #pragma unroll
        for (int kk = 0; kk < 4; kk++) {
            int c = kk * 16 + 2 * tig;
            aq[mf][kk][0] = *(const uint32_t*)&Q0[c];
            aq[mf][kk][1] = *(const uint32_t*)&Q0[8 * HDIM + c];
            aq[mf][kk][2] = *(const uint32_t*)&Q0[c + 8];
            aq[mf][kk][3] = *(const uint32_t*)&Q0[8 * HDIM + c + 8];
        }
    }

    float oacc[2][8][4];
    #pragma unroll
    for (int mf = 0; mf < 2; mf++)
        #pragma unroll
        for (int ni = 0; ni < 8; ni++)
            #pragma unroll
            for (int j = 0; j < 4; j++) oacc[mf][ni][j] = 0.f;
    float mx[4] = {-1e30f, -1e30f, -1e30f, -1e30f};
    float lv[4] = {0.f, 0.f, 0.f, 0.f};

    const __half* Kg  = g_K + base;
    const __half* Vtg = g_V + base;

    attn_load(smb, 0, Kg, Vtg, 0, tid);
    attn_load(smb, 1, Kg, Vtg, 1, tid);

    for (int kt = 0; kt <= lim; kt++) {
        if (kt < lim) cpwait<1>(); else cpwait<0>();
        __syncthreads();
        if (kt + 2 <= lim)
            attn_load(smb, (kt + 2) % 3, Kg, Vtg, kt + 2, tid);

        if (kt <= mylim) {
            const __half* Ks = smh + (kt % 3) * 9216;
            const __half* Vt = Ks + 4608;

            // S = Q @ K^T  (keys = n, dims = k); each b frag feeds 2 mma
            float sc[2][8][4];
            #pragma unroll
            for (int mf = 0; mf < 2; mf++)
                #pragma unroll
                for (int ni = 0; ni < 8; ni++)
                    #pragma unroll
                    for (int j = 0; j < 4; j++) sc[mf][ni][j] = 0.f;
            #pragma unroll
            for (int kk = 0; kk < 4; kk++) {
                uint32_t b[8][2];
                #pragma unroll
                for (int ni = 0; ni < 8; ni++) {
                    int cb = (ni * 8 + g) * 72 + kk * 16 + 2 * tig;
                    b[ni][0] = *(const uint32_t*)&Ks[cb];
                    b[ni][1] = *(const uint32_t*)&Ks[cb + 8];
                }
                #pragma unroll
                for (int mf = 0; mf < 2; mf++)
                    #pragma unroll
                    for (int ni = 0; ni < 8; ni++)
                        mmaf16(sc[mf][ni], aq[mf][kk], b[ni]);
            }

            // scale (log2 domain) + causal mask on diagonal tile + row max
            const bool diag = (kt == mylim);
            float nm[4] = {mx[0], mx[1], mx[2], mx[3]};
            #pragma unroll
            for (int mf = 0; mf < 2; mf++) {
                const int rowA = rbase + mf * 16 + g;
                const int rowB = rowA + 8;
                #pragma unroll
                for (int ni = 0; ni < 8; ni++) {
                    int col = kt * 64 + ni * 8 + 2 * tig;
                    #pragma unroll
                    for (int j = 0; j < 4; j++) sc[mf][ni][j] *= SCL;
                    if (diag) {
                        if (col     > rowA) sc[mf][ni][0] = -1e30f;
                        if (col + 1 > rowA) sc[mf][ni][1] = -1e30f;
                        if (col     > rowB) sc[mf][ni][2] = -1e30f;
                        if (col + 1 > rowB) sc[mf][ni][3] = -1e30f;
                    }
                    nm[2*mf]   = fmaxf(nm[2*mf],   fmaxf(sc[mf][ni][0], sc[mf][ni][1]));
                    nm[2*mf+1] = fmaxf(nm[2*mf+1], fmaxf(sc[mf][ni][2], sc[mf][ni][3]));
                }
            }
            #pragma unroll
            for (int j = 0; j < 4; j++) {
                nm[j] = fmaxf(nm[j], __shfl_xor_sync(0xffffffffu, nm[j], 1));
                nm[j] = fmaxf(nm[j], __shfl_xor_sync(0xffffffffu, nm[j], 2));
            }
            float corr[4];
            #pragma unroll
            for (int j = 0; j < 4; j++) {
                corr[j] = ex2(mx[j] - nm[j]);
                mx[j] = nm[j];
            }

            // exp in place; accumulate row sums
            float ls[4] = {0.f, 0.f, 0.f, 0.f};
            #pragma unroll
            for (int mf = 0; mf < 2; mf++)
                #pragma unroll
                for (int ni = 0; ni < 8; ni++) {
                    sc[mf][ni][0] = ex2(sc[mf][ni][0] - mx[2*mf]);
                    sc[mf][ni][1] = ex2(sc[mf][ni][1] - mx[2*mf]);
                    sc[mf][ni][2] = ex2(sc[mf][ni][2] - mx[2*mf+1]);
                    sc[mf][ni][3] = ex2(sc[mf][ni][3] - mx[2*mf+1]);
                    ls[2*mf]   += sc[mf][ni][0] + sc[mf][ni][1];
                    ls[2*mf+1] += sc[mf][ni][2] + sc[mf][ni][3];
                }
            #pragma unroll
            for (int j = 0; j < 4; j++) lv[j] = lv[j] * corr[j] + ls[j];
            #pragma unroll
            for (int mf = 0; mf < 2; mf++)
                #pragma unroll
                for (int ni = 0; ni < 8; ni++) {
                    oacc[mf][ni][0] *= corr[2*mf];   oacc[mf][ni][1] *= corr[2*mf];
                    oacc[mf][ni][2] *= corr[2*mf+1]; oacc[mf][ni][3] *= corr[2*mf+1];
                }

            // O += P @ V  (dims = n via Vt rows, keys = k); b feeds 2 mma
            #pragma unroll
            for (int kk = 0; kk < 4; kk++) {
                uint32_t pa[2][4];
                #pragma unroll
                for (int mf = 0; mf < 2; mf++) {
                    pa[mf][0] = h2(sc[mf][2*kk][0],   sc[mf][2*kk][1]);
                    pa[mf][1] = h2(sc[mf][2*kk][2],   sc[mf][2*kk][3]);
                    pa[mf][2] = h2(sc[mf][2*kk+1][0], sc[mf][2*kk+1][1]);
                    pa[mf][3] = h2(sc[mf][2*kk+1][2], sc[mf][2*kk+1][3]);
                }
                uint32_t b[8][2];
                #pragma unroll
                for (int ni = 0; ni < 8; ni++) {
                    int cb = (ni * 8 + g) * 72 + kk * 16 + 2 * tig;
                    b[ni][0] = *(const uint32_t*)&Vt[cb];
                    b[ni][1] = *(const uint32_t*)&Vt[cb + 8];
                }
                #pragma unroll
                for (int mf = 0; mf < 2; mf++)
                    #pragma unroll
                    for (int ni = 0; ni < 8; ni++)
                        mmaf16(oacc[mf][ni], pa[mf], b[ni]);
            }
        }
    }

    // Finalize
    #pragma unroll
    for (int j = 0; j < 4; j++) {
        lv[j] += __shfl_xor_sync(0xffffffffu, lv[j], 1);
        lv[j] += __shfl_xor_sync(0xffffffffu, lv[j], 2);
        lv[j] = 1.f / lv[j];
    }
    const int b = bh >> 4, h = bh & 15;
    #pragma unroll
    for (int mf = 0; mf < 2; mf++) {
        const int rowA = rbase + mf * 16 + g;
        #pragma unroll
        for (int ni = 0; ni < 8; ni++) {
            int col = ni * 8 + 2 * tig;
            size_t o0 = ((size_t)(b * SS + rowA)) * DD + h * HDIM + col;
            size_t o1 = ((size_t)(b * SS + rowA + 8)) * DD + h * HDIM + col;
            *(uint32_t*)&g_AO[o0] = h2(oacc[mf][ni][0] * lv[2*mf],
                                       oacc[mf][ni][1] * lv[2*mf]);
            *(uint32_t*)&g_AO[o1] = h2(oacc[mf][ni][2] * lv[2*mf+1],
                                       oacc[mf][ni][3] * lv[2*mf+1]);
        }
    }
}

// ---------------------------------------------------------------------------
extern "C" void kernel_launch(void* const* d_in, const int* in_sizes, int n_in,
                              void* d_out, int out_size)
{
    const float* x  = (const float*)d_in[0];
    const float* fc = (const float*)d_in[1];
    const float* fs = (const float*)d_in[2];
    float* out = (float*)d_out;

    // One-time infra (created on the uncaptured correctness call; no device
    // memory allocation involved). Work per call is identical.
    static cudaStream_t s1 = nullptr, s2 = nullptr;
    static cudaEvent_t e0 = nullptr, f1 = nullptr, f2 = nullptr;
    static bool attr_done = false;
    if (!attr_done) {
        cudaStreamCreateWithFlags(&s1, cudaStreamNonBlocking);
        cudaStreamCreateWithFlags(&s2, cudaStreamNonBlocking);
        cudaEventCreateWithFlags(&e0, cudaEventDisableTiming);
        cudaEventCreateWithFlags(&f1, cudaEventDisableTiming);
        cudaEventCreateWithFlags(&f2, cudaEventDisableTiming);
        const int gs = 3 * 36864, as = 3 * 18432;
        cudaFuncSetAttribute(qkv_f16, cudaFuncAttributeMaxDynamicSharedMemorySize, gs);
        cudaFuncSetAttribute(gemm_o,  cudaFuncAttributeMaxDynamicSharedMemorySize, gs);
        cudaFuncSetAttribute(attn_f16, cudaFuncAttributeMaxDynamicSharedMemorySize, as);
        attr_done = true;
    }
    const int gemm_smem = 3 * 36864;   // 110592
    const int attn_smem = 3 * 18432;   // 55296

    const int ncvt = N4X + 4 * N4W;    // 3145728
    cvt_all<<<ncvt / 1024, 256>>>((const float4*)x,
                                  (const float4*)d_in[3], (const float4*)d_in[4],
                                  (const float4*)d_in[5], (const float4*)d_in[6]);
    cudaEventRecord(e0, 0);
    cudaStreamWaitEvent(s1, e0, 0);
    cudaStreamWaitEvent(s2, e0, 0);

    // Batch halves pipelined on two streams: qkv -> attn -> gemm_o per half.
    dim3 gq(DD / 128, MM / 256, 3);    // (8, 32, 3)
    dim3 ag(SS / 128, BB * HH / 2);    // (16, 32)
    dim3 go(DD / 128, MM / 256);       // (8, 32)

    qkv_f16<<<gq, 128, gemm_smem, s1>>>(fc, fs, 0);
    attn_f16<<<ag, 128, attn_smem, s1>>>(0);
    gemm_o<<<go, 128, gemm_smem, s1>>>(out, 0);

    qkv_f16<<<gq, 128, gemm_smem, s2>>>(fc, fs, 32);
    attn_f16<<<ag, 128, attn_smem, s2>>>(32);
    gemm_o<<<go, 128, gemm_smem, s2>>>(out, 32);

    cudaEventRecord(f1, s1);
    cudaEventRecord(f2, s2);
    cudaStreamWaitEvent(0, f1, 0);
    cudaStreamWaitEvent(0, f2, 0);
}

// round 17
// speedup vs baseline: 1.6561x; 1.0052x over previous
#include <cuda_runtime.h>
#include <cuda_fp16.h>
#include <stdint.h>

#define BB 4
#define SS 2048
#define DD 1024
#define HH 16
#define HDIM 64
#define MM (BB*SS)   // 8192

// Scratch (allocation-free rule: __device__ globals). All fp16.
__device__ __half g_Xt[(size_t)MM*DD];
__device__ __half g_Wt[(size_t)4*DD*DD];    // wq,wk,wv,wo
__device__ __half g_Q [(size_t)MM*DD];      // [B,H,S,HD]
__device__ __half g_K [(size_t)MM*DD];
__device__ __half g_V [(size_t)MM*DD];      // TRANSPOSED: [B,H,HD,S]
__device__ __half g_AO[(size_t)MM*DD];      // [B,S,D]

__device__ __forceinline__ float ex2(float x) {
    float r;
    asm("ex2.approx.f32 %0, %1;" : "=f"(r) : "f"(x));
    return r;
}
__device__ __forceinline__ uint32_t h2(float a, float b) {
    __half2 h = __floats2half2_rn(a, b);
    return *(uint32_t*)&h;
}
__device__ __forceinline__ void mmaf16(float* c, const uint32_t* a, const uint32_t* b) {
    asm volatile(
        "mma.sync.aligned.m16n8k16.row.col.f32.f16.f16.f32 "
        "{%0,%1,%2,%3},{%4,%5,%6,%7},{%8,%9},{%0,%1,%2,%3};"
        : "+f"(c[0]), "+f"(c[1]), "+f"(c[2]), "+f"(c[3])
        : "r"(a[0]), "r"(a[1]), "r"(a[2]), "r"(a[3]), "r"(b[0]), "r"(b[1]));
}
__device__ __forceinline__ void cpa16(uint32_t dst, const void* src) {
    asm volatile("cp.async.cg.shared.global [%0], [%1], 16;" :: "r"(dst), "l"(src));
}
__device__ __forceinline__ void cpcommit() {
    asm volatile("cp.async.commit_group;");
}
template<int N> __device__ __forceinline__ void cpwait() {
    asm volatile("cp.async.wait_group %0;" :: "n"(N));
}

// ---------------------------------------------------------------------------
// Split prepass: fp32 -> fp16 (RN), ILP=4, stream-resident.
// cvt_a: x rows [0, MM/2) + wq,wk,wv   (feeds qkv0 on the same stream)
// cvt_b: x rows [MM/2, MM) + wo        (feeds qkv1 / gemm_o1)
// Same per-element conversion and destinations as the fused version.
// ---------------------------------------------------------------------------
#define N4X  (MM*DD/4)      // 2097152
#define N4XH (N4X/2)        // 1048576
#define N4W  (DD*DD/4)      // 262144 = 2^18
#define NA4  (N4XH + 3*N4W) // 1835008 -> /4 /256 = 1792 blocks
#define NB4  (N4XH + N4W)   // 1310720 -> /4 /256 = 1280 blocks

__device__ __forceinline__ void cvt_a_one(int i, const float4* x,
        const float4* wq, const float4* wk, const float4* wv) {
    const float4* src;
    __half* dst;
    int j;
    if (i < N4XH) {
        src = x; dst = g_Xt; j = i;
    } else {
        int k = i - N4XH;
        int w = k >> 18;
        j = k & (N4W - 1);
        src = (w == 0) ? wq : (w == 1) ? wk : wv;
        dst = g_Wt + (size_t)w * DD * DD;
    }
    float4 v = src[j];
    *(uint2*)&dst[(size_t)j * 4] = make_uint2(h2(v.x, v.y), h2(v.z, v.w));
}
__global__ void cvt_a(const float4* __restrict__ x, const float4* __restrict__ wq,
                      const float4* __restrict__ wk, const float4* __restrict__ wv) {
    int i = blockIdx.x * 1024 + threadIdx.x;
    cvt_a_one(i,       x, wq, wk, wv);
    cvt_a_one(i + 256, x, wq, wk, wv);
    cvt_a_one(i + 512, x, wq, wk, wv);
    cvt_a_one(i + 768, x, wq, wk, wv);
}
__device__ __forceinline__ void cvt_b_one(int i, const float4* x,
                                          const float4* wo) {
    if (i < N4XH) {
        int j = N4XH + i;
        float4 v = x[j];
        *(uint2*)&g_Xt[(size_t)j * 4] = make_uint2(h2(v.x, v.y), h2(v.z, v.w));
    } else {
        int j = i - N4XH;
        float4 v = wo[j];
        *(uint2*)&g_Wt[(size_t)3 * DD * DD + (size_t)j * 4] =
            make_uint2(h2(v.x, v.y), h2(v.z, v.w));
    }
}
__global__ void cvt_b(const float4* __restrict__ x, const float4* __restrict__ wo) {
    int i = blockIdx.x * 1024 + threadIdx.x;
    cvt_b_one(i,       x, wo);
    cvt_b_one(i + 256, x, wo);
    cvt_b_one(i + 512, x, wo);
    cvt_b_one(i + 768, x, wo);
}

// ---------------------------------------------------------------------------
// Shared GEMM mainloop: acc = A[M,K] @ B[N,K]^T for one 128x128 CTA tile.
// 128 threads = 4 warps x 64x64 warp tiles. K-slab 64, 3-stage cp.async,
// one barrier per iteration. Scalar-LDS fragments.
// ---------------------------------------------------------------------------
__device__ __forceinline__ void g_load(uint32_t smb, int s,
                                       const __half* Ag, const __half* Bg,
                                       int m0, int n0, int k0, int tid) {
    uint32_t sa = smb + (uint32_t)s * 36864u;
    uint32_t sb = sa + 18432u;
    #pragma unroll
    for (int i = 0; i < 8; i++) {
        int c = tid + i * 128;
        int r = c >> 3, cb = (c & 7) * 16;
        cpa16(sa + (uint32_t)(r * 144 + cb), Ag + (size_t)(m0 + r) * DD + k0 + (c & 7) * 8);
    }
    #pragma unroll
    for (int i = 0; i < 8; i++) {
        int c = tid + i * 128;
        int r = c >> 3, cb = (c & 7) * 16;
        cpa16(sb + (uint32_t)(r * 144 + cb), Bg + (size_t)(n0 + r) * DD + k0 + (c & 7) * 8);
    }
    cpcommit();
}

__device__ __forceinline__ void run_gemm(float acc[4][8][4],
                                         const __half* Ag, const __half* Bg,
                                         int m0, int n0, __half* smh, int tid)
{
    const int warp = tid >> 5, lane = tid & 31;
    const int wm = warp & 1, wn = warp >> 1;
    const int g = lane >> 2, tig = lane & 3;
    const uint32_t smb = (uint32_t)__cvta_generic_to_shared(smh);

    g_load(smb, 0, Ag, Bg, m0, n0, 0,  tid);
    g_load(smb, 1, Ag, Bg, m0, n0, 64, tid);

    for (int t = 0; t < 16; t++) {
        if (t < 15) cpwait<1>(); else cpwait<0>();
        __syncthreads();
        if (t + 2 < 16)
            g_load(smb, (t + 2) % 3, Ag, Bg, m0, n0, (t + 2) * 64, tid);

        const __half* As = smh + (t % 3) * 18432;
        const __half* Bs = As + 9216;
        #pragma unroll
        for (int ks = 0; ks < 4; ks++) {
            uint32_t a[4][4], b[8][2];
            #pragma unroll
            for (int mi = 0; mi < 4; mi++) {
                int cb = (wm * 64 + mi * 16 + g) * 72 + ks * 16 + 2 * tig;
                a[mi][0] = *(const uint32_t*)&As[cb];
                a[mi][1] = *(const uint32_t*)&As[cb + 8 * 72];
                a[mi][2] = *(const uint32_t*)&As[cb + 8];
                a[mi][3] = *(const uint32_t*)&As[cb + 8 * 72 + 8];
            }
            #pragma unroll
            for (int ni = 0; ni < 8; ni++) {
                int cb = (wn * 64 + ni * 8 + g) * 72 + ks * 16 + 2 * tig;
                b[ni][0] = *(const uint32_t*)&Bs[cb];
                b[ni][1] = *(const uint32_t*)&Bs[cb + 8];
            }
            #pragma unroll
            for (int mi = 0; mi < 4; mi++)
                #pragma unroll
                for (int ni = 0; ni < 8; ni++)
                    mmaf16(acc[mi][ni], a[mi], b[ni]);
        }
    }
}

// ---------------------------------------------------------------------------
// Fused QKV projection: z = 0/1/2 -> Q/K (RoPE) / V (transposed write).
// my0: m-tile offset (batch split for stream overlap).
// ---------------------------------------------------------------------------
__global__ __launch_bounds__(128, 2)
void qkv_f16(const float* __restrict__ fc, const float* __restrict__ fs, int my0)
{
    extern __shared__ __half smh[];
    const int tid = threadIdx.x;
    const int m0 = (blockIdx.y + my0) * 128, n0 = blockIdx.x * 128;
    const int z = blockIdx.z;
    const int warp = tid >> 5, lane = tid & 31;
    const int wm = warp & 1, wn = warp >> 1;
    const int g = lane >> 2, tig = lane & 3;

    float acc[4][8][4];
    #pragma unroll
    for (int mi = 0; mi < 4; mi++)
        #pragma unroll
        for (int ni = 0; ni < 8; ni++)
            #pragma unroll
            for (int j = 0; j < 4; j++) acc[mi][ni][j] = 0.f;

    run_gemm(acc, g_Xt, g_Wt + (size_t)z * DD * DD, m0, n0, smh, tid);

    #pragma unroll
    for (int mi = 0; mi < 4; mi++) {
        #pragma unroll
        for (int ni = 0; ni < 8; ni++) {
            const int m = m0 + wm * 64 + mi * 16 + g;
            const int n = n0 + wn * 64 + ni * 8 + 2 * tig;
            float c0 = acc[mi][ni][0], c1 = acc[mi][ni][1];
            float c2 = acc[mi][ni][2], c3 = acc[mi][ni][3];
            const int b = m >> 11, sl = m & (SS - 1);
            const int h = n >> 6, d = n & 63;
            const int bh = b * HH + h;
            if (z == 2) {
                size_t ov = ((size_t)bh * HDIM + d) * SS + sl;
                g_V[ov]          = __float2half_rn(c0);
                g_V[ov + SS]     = __float2half_rn(c1);
                g_V[ov + 8]      = __float2half_rn(c2);
                g_V[ov + SS + 8] = __float2half_rn(c3);
            } else {
                const int f = d >> 1;
                float cA = fc[sl * 32 + f],       sA = fs[sl * 32 + f];
                float cB = fc[(sl + 8) * 32 + f], sB = fs[(sl + 8) * 32 + f];
                float v0 = c0 * cA - c1 * sA, v1 = c0 * sA + c1 * cA;
                float v2 = c2 * cB - c3 * sB, v3 = c2 * sB + c3 * cB;
                __half* dstq = (z == 0) ? g_Q : g_K;
                size_t o = ((size_t)bh * SS + sl) * HDIM + d;
                *(uint32_t*)&dstq[o]            = h2(v0, v1);
                *(uint32_t*)&dstq[o + 8 * HDIM] = h2(v2, v3);
            }
        }
    }
}

// ---------------------------------------------------------------------------
// Output projection: g_AO @ wo -> fp32 out. my0: m-tile offset (batch split).
// ---------------------------------------------------------------------------
__global__ __launch_bounds__(128, 2)
void gemm_o(float* __restrict__ out, int my0)
{
    extern __shared__ __half smh[];
    const int tid = threadIdx.x;
    const int m0 = (blockIdx.y + my0) * 128, n0 = blockIdx.x * 128;
    const int warp = tid >> 5, lane = tid & 31;
    const int wm = warp & 1, wn = warp >> 1;
    const int g = lane >> 2, tig = lane & 3;

    float acc[4][8][4];
    #pragma unroll
    for (int mi = 0; mi < 4; mi++)
        #pragma unroll
        for (int ni = 0; ni < 8; ni++)
            #pragma unroll
            for (int j = 0; j < 4; j++) acc[mi][ni][j] = 0.f;

    run_gemm(acc, g_AO, g_Wt + (size_t)3 * DD * DD, m0, n0, smh, tid);

    #pragma unroll
    for (int mi = 0; mi < 4; mi++) {
        #pragma unroll
        for (int ni = 0; ni < 8; ni++) {
            const int m = m0 + wm * 64 + mi * 16 + g;
            const int n = n0 + wn * 64 + ni * 8 + 2 * tig;
            *(float2*)&out[(size_t)m * DD + n] =
                make_float2(acc[mi][ni][0], acc[mi][ni][1]);
            *(float2*)&out[(size_t)(m + 8) * DD + n] =
                make_float2(acc[mi][ni][2], acc[mi][ni][3]);
        }
    }
}

// ---------------------------------------------------------------------------
// Flash attention fp16. 128 thr = 4 warps x 32 q-rows; 128 q rows/CTA;
// 64-key tiles, 3-stage cp.async, one barrier/iter. bh0: head-batch offset.
// Smem: stage s at s*18432 B (K 9216 + Vt 9216). Total 55296 B.
// ---------------------------------------------------------------------------
__device__ __forceinline__ void attn_load(uint32_t smb, int stage,
                                          const __half* Kg, const __half* Vtg,
                                          int kt, int tid) {
    uint32_t ks = smb + (uint32_t)stage * 18432u;
    uint32_t vs = ks + 9216u;
    #pragma unroll
    for (int i = 0; i < 4; i++) {
        int c = tid + i * 128;
        int r = c >> 3, cb = (c & 7) * 16;
        cpa16(ks + (uint32_t)(r * 144 + cb), Kg + (size_t)(kt * 64 + r) * HDIM + (c & 7) * 8);
        cpa16(vs + (uint32_t)(r * 144 + cb), Vtg + (size_t)r * SS + kt * 64 + (c & 7) * 8);
    }
    cpcommit();
}

#define SCL 0.18033688f   // 0.125 * log2(e)

__global__ __launch_bounds__(128, 2)
void attn_f16(int bh0)
{
    extern __shared__ __half smh[];
    const int tid = threadIdx.x, warp = tid >> 5, lane = tid & 31;
    const int g = lane >> 2, tig = lane & 3;
    const int qb = gridDim.x - 1 - blockIdx.x;   // heaviest tiles first
    const int bh = blockIdx.y + bh0;
    const size_t base = (size_t)bh * SS * HDIM;
    const int lim = 2 * qb + 1;
    const int mylim = 2 * qb + (warp >> 1);      // warps 0,1 skip last tile
    const int rbase = qb * 128 + warp * 32;
    const uint32_t smb = (uint32_t)__cvta_generic_to_shared(smh);

    // Q fragments, 2 m-frags of 16 rows. aq[mf][kk] covers dims 16kk..+15.
    uint32_t aq[2][4][4];
    #pragma unroll
    for (int mf = 0; mf < 2; mf++) {
        const __half* Q0 = g_Q + base + (size_t)(rbase + mf * 16 + g) * HDIM;
        #pragma unroll
        for (int kk = 0; kk < 4; kk++) {
            int c = kk * 16 + 2 * tig;
            aq[mf][kk][0] = *(const uint32_t*)&Q0[c];
            aq[mf][kk][1] = *(const uint32_t*)&Q0[8 * HDIM + c];
            aq[mf][kk][2] = *(const uint32_t*)&Q0[c + 8];
            aq[mf][kk][3] = *(const uint32_t*)&Q0[8 * HDIM + c + 8];
        }
    }

    float oacc[2][8][4];
    #pragma unroll
    for (int mf = 0; mf < 2; mf++)
        #pragma unroll
        for (int ni = 0; ni < 8; ni++)
            #pragma unroll
            for (int j = 0; j < 4; j++) oacc[mf][ni][j] = 0.f;
    float mx[4] = {-1e30f, -1e30f, -1e30f, -1e30f};
    float lv[4] = {0.f, 0.f, 0.f, 0.f};

    const __half* Kg  = g_K + base;
    const __half* Vtg = g_V + base;

    attn_load(smb, 0, Kg, Vtg, 0, tid);
    attn_load(smb, 1, Kg, Vtg, 1, tid);

    for (int kt = 0; kt <= lim; kt++) {
        if (kt < lim) cpwait<1>(); else cpwait<0>();
        __syncthreads();
        if (kt + 2 <= lim)
            attn_load(smb, (kt + 2) % 3, Kg, Vtg, kt + 2, tid);

        if (kt <= mylim) {
            const __half* Ks = smh + (kt % 3) * 9216;
            const __half* Vt = Ks + 4608;

            // S = Q @ K^T  (keys = n, dims = k); each b frag feeds 2 mma
            float sc[2][8][4];
            #pragma unroll
            for (int mf = 0; mf < 2; mf++)
                #pragma unroll
                for (int ni = 0; ni < 8; ni++)
                    #pragma unroll
                    for (int j = 0; j < 4; j++) sc[mf][ni][j] = 0.f;
            #pragma unroll
            for (int kk = 0; kk < 4; kk++) {
                uint32_t b[8][2];
                #pragma unroll
                for (int ni = 0; ni < 8; ni++) {
                    int cb = (ni * 8 + g) * 72 + kk * 16 + 2 * tig;
                    b[ni][0] = *(const uint32_t*)&Ks[cb];
                    b[ni][1] = *(const uint32_t*)&Ks[cb + 8];
                }
                #pragma unroll
                for (int mf = 0; mf < 2; mf++)
                    #pragma unroll
                    for (int ni = 0; ni < 8; ni++)
                        mmaf16(sc[mf][ni], aq[mf][kk], b[ni]);
            }

            // scale (log2 domain) + causal mask on diagonal tile + row max
            const bool diag = (kt == mylim);
            float nm[4] = {mx[0], mx[1], mx[2], mx[3]};
            #pragma unroll
            for (int mf = 0; mf < 2; mf++) {
                const int rowA = rbase + mf * 16 + g;
                const int rowB = rowA + 8;
                #pragma unroll
                for (int ni = 0; ni < 8; ni++) {
                    int col = kt * 64 + ni * 8 + 2 * tig;
                    #pragma unroll
                    for (int j = 0; j < 4; j++) sc[mf][ni][j] *= SCL;
                    if (diag) {
                        if (col     > rowA) sc[mf][ni][0] = -1e30f;
                        if (col + 1 > rowA) sc[mf][ni][1] = -1e30f;
                        if (col     > rowB) sc[mf][ni][2] = -1e30f;
                        if (col + 1 > rowB) sc[mf][ni][3] = -1e30f;
                    }
                    nm[2*mf]   = fmaxf(nm[2*mf],   fmaxf(sc[mf][ni][0], sc[mf][ni][1]));
                    nm[2*mf+1] = fmaxf(nm[2*mf+1], fmaxf(sc[mf][ni][2], sc[mf][ni][3]));
                }
            }
            #pragma unroll
            for (int j = 0; j < 4; j++) {
                nm[j] = fmaxf(nm[j], __shfl_xor_sync(0xffffffffu, nm[j], 1));
                nm[j] = fmaxf(nm[j], __shfl_xor_sync(0xffffffffu, nm[j], 2));
            }
            float corr[4];
            #pragma unroll
            for (int j = 0; j < 4; j++) {
                corr[j] = ex2(mx[j] - nm[j]);
                mx[j] = nm[j];
            }

            // exp in place; accumulate row sums
            float ls[4] = {0.f, 0.f, 0.f, 0.f};
            #pragma unroll
            for (int mf = 0; mf < 2; mf++)
                #pragma unroll
                for (int ni = 0; ni < 8; ni++) {
                    sc[mf][ni][0] = ex2(sc[mf][ni][0] - mx[2*mf]);
                    sc[mf][ni][1] = ex2(sc[mf][ni][1] - mx[2*mf]);
                    sc[mf][ni][2] = ex2(sc[mf][ni][2] - mx[2*mf+1]);
                    sc[mf][ni][3] = ex2(sc[mf][ni][3] - mx[2*mf+1]);
                    ls[2*mf]   += sc[mf][ni][0] + sc[mf][ni][1];
                    ls[2*mf+1] += sc[mf][ni][2] + sc[mf][ni][3];
                }
            #pragma unroll
            for (int j = 0; j < 4; j++) lv[j] = lv[j] * corr[j] + ls[j];
            #pragma unroll
            for (int mf = 0; mf < 2; mf++)
                #pragma unroll
                for (int ni = 0; ni < 8; ni++) {
                    oacc[mf][ni][0] *= corr[2*mf];   oacc[mf][ni][1] *= corr[2*mf];
                    oacc[mf][ni][2] *= corr[2*mf+1]; oacc[mf][ni][3] *= corr[2*mf+1];
                }

            // O += P @ V  (dims = n via Vt rows, keys = k); b feeds 2 mma
            #pragma unroll
            for (int kk = 0; kk < 4; kk++) {
                uint32_t pa[2][4];
                #pragma unroll
                for (int mf = 0; mf < 2; mf++) {
                    pa[mf][0] = h2(sc[mf][2*kk][0],   sc[mf][2*kk][1]);
                    pa[mf][1] = h2(sc[mf][2*kk][2],   sc[mf][2*kk][3]);
                    pa[mf][2] = h2(sc[mf][2*kk+1][0], sc[mf][2*kk+1][1]);
                    pa[mf][3] = h2(sc[mf][2*kk+1][2], sc[mf][2*kk+1][3]);
                }
                uint32_t b[8][2];
                #pragma unroll
                for (int ni = 0; ni < 8; ni++) {
                    int cb = (ni * 8 + g) * 72 + kk * 16 + 2 * tig;
                    b[ni][0] = *(const uint32_t*)&Vt[cb];
                    b[ni][1] = *(const uint32_t*)&Vt[cb + 8];
                }
                #pragma unroll
                for (int mf = 0; mf < 2; mf++)
                    #pragma unroll
                    for (int ni = 0; ni < 8; ni++)
                        mmaf16(oacc[mf][ni], pa[mf], b[ni]);
            }
        }
    }

    // Finalize
    #pragma unroll
    for (int j = 0; j < 4; j++) {
        lv[j] += __shfl_xor_sync(0xffffffffu, lv[j], 1);
        lv[j] += __shfl_xor_sync(0xffffffffu, lv[j], 2);
        lv[j] = 1.f / lv[j];
    }
    const int b = bh >> 4, h = bh & 15;
    #pragma unroll
    for (int mf = 0; mf < 2; mf++) {
        const int rowA = rbase + mf * 16 + g;
        #pragma unroll
        for (int ni = 0; ni < 8; ni++) {
            int col = ni * 8 + 2 * tig;
            size_t o0 = ((size_t)(b * SS + rowA)) * DD + h * HDIM + col;
            size_t o1 = ((size_t)(b * SS + rowA + 8)) * DD + h * HDIM + col;
            *(uint32_t*)&g_AO[o0] = h2(oacc[mf][ni][0] * lv[2*mf],
                                       oacc[mf][ni][1] * lv[2*mf]);
            *(uint32_t*)&g_AO[o1] = h2(oacc[mf][ni][2] * lv[2*mf+1],
                                       oacc[mf][ni][3] * lv[2*mf+1]);
        }
    }
}

// ---------------------------------------------------------------------------
extern "C" void kernel_launch(void* const* d_in, const int* in_sizes, int n_in,
                              void* d_out, int out_size)
{
    const float* x  = (const float*)d_in[0];
    const float* fc = (const float*)d_in[1];
    const float* fs = (const float*)d_in[2];
    float* out = (float*)d_out;

    // One-time infra (created on the uncaptured correctness call; no device
    // memory allocation involved). Work per call is identical.
    static cudaStream_t s1 = nullptr, s2 = nullptr;
    static cudaEvent_t eA = nullptr, eB = nullptr, f1 = nullptr, f2 = nullptr, e0 = nullptr;
    static bool attr_done = false;
    if (!attr_done) {
        cudaStreamCreateWithFlags(&s1, cudaStreamNonBlocking);
        cudaStreamCreateWithFlags(&s2, cudaStreamNonBlocking);
        cudaEventCreateWithFlags(&e0, cudaEventDisableTiming);
        cudaEventCreateWithFlags(&eA, cudaEventDisableTiming);
        cudaEventCreateWithFlags(&eB, cudaEventDisableTiming);
        cudaEventCreateWithFlags(&f1, cudaEventDisableTiming);
        cudaEventCreateWithFlags(&f2, cudaEventDisableTiming);
        const int gs = 3 * 36864, as = 3 * 18432;
        cudaFuncSetAttribute(qkv_f16, cudaFuncAttributeMaxDynamicSharedMemorySize, gs);
        cudaFuncSetAttribute(gemm_o,  cudaFuncAttributeMaxDynamicSharedMemorySize, gs);
        cudaFuncSetAttribute(attn_f16, cudaFuncAttributeMaxDynamicSharedMemorySize, as);
        attr_done = true;
    }
    const int gemm_smem = 3 * 36864;   // 110592
    const int attn_smem = 3 * 18432;   // 55296

    // Fork both streams from the capture (default) stream.
    cudaEventRecord(e0, 0);
    cudaStreamWaitEvent(s1, e0, 0);
    cudaStreamWaitEvent(s2, e0, 0);

    dim3 gq(DD / 128, MM / 256, 3);    // (8, 32, 3)
    dim3 ag(SS / 128, BB * HH / 2);    // (16, 32)
    dim3 go(DD / 128, MM / 256);       // (8, 32)

    // s1: cvt_a (x half0 + wq,wk,wv) -> qkv0 -> attn0 -> [wait wo] gemm_o0
    cvt_a<<<NA4 / 1024, 256, 0, s1>>>((const float4*)x, (const float4*)d_in[3],
                                      (const float4*)d_in[4], (const float4*)d_in[5]);
    cudaEventRecord(eA, s1);
    qkv_f16<<<gq, 128, gemm_smem, s1>>>(fc, fs, 0);
    attn_f16<<<ag, 128, attn_smem, s1>>>(0);

    // s2: cvt_b (x half1 + wo) -> [wait weights] qkv1 -> attn1 -> gemm_o1
    cvt_b<<<NB4 / 1024, 256, 0, s2>>>((const float4*)x, (const float4*)d_in[6]);
    cudaEventRecord(eB, s2);
    cudaStreamWaitEvent(s2, eA, 0);    // qkv1 needs wq,wk,wv (+x half1 own-stream)
    qkv_f16<<<gq, 128, gemm_smem, s2>>>(fc, fs, 32);
    attn_f16<<<ag, 128, attn_smem, s2>>>(32);
    gemm_o<<<go, 128, gemm_smem, s2>>>(out, 32);

    cudaStreamWaitEvent(s1, eB, 0);    // gemm_o0 needs wo from cvt_b
    gemm_o<<<go, 128, gemm_smem, s1>>>(out, 0);

    // Join back to the capture stream.
    cudaEventRecord(f1, s1);
    cudaEventRecord(f2, s2);
    cudaStreamWaitEvent(0, f1, 0);
    cudaStreamWaitEvent(0, f2, 0);
}